// round 1
// baseline (speedup 1.0000x reference)
#include <cuda_runtime.h>
#include <math.h>

// Problem shape (hardcoded per reference): B=4, S=4096, D=1024, H=64
#define B_ 4
#define S_ 4096
#define D_ 1024
#define H_ 64
#define NROWS (B_ * S_)   // 16384

// Scratch for Q/K/V projections (allocation-free: __device__ globals)
__device__ float g_q[NROWS * H_];
__device__ float g_k[NROWS * H_];
__device__ float g_v[NROWS * H_];

// ---------------------------------------------------------------------------
// Kernel 1: fused QKV projection + LayerNorm (Q,K only).
// Grid: (NROWS/128, 3). Block: 256 threads. Each block computes a 128x64 tile
// of one of Q/K/V, then row-wise LayerNorm for Q and K.
// ---------------------------------------------------------------------------
__global__ __launch_bounds__(256) void proj_ln_kernel(
    const float* __restrict__ X,
    const float* __restrict__ Wq,
    const float* __restrict__ Wk,
    const float* __restrict__ Wv)
{
    __shared__ float As[16][132];   // A^T tile: As[k][m], padded
    __shared__ float Bs[16][64];    // W tile:  Bs[k][n]
    __shared__ float Cs[128][68];   // C tile for LayerNorm reduction (pad 68 -> 16B aligned rows)
    __shared__ float mu_s[128];
    __shared__ float rs_s[128];

    const int mt    = blockIdx.x;           // row tile (128 rows)
    const int which = blockIdx.y;           // 0=Q, 1=K, 2=V
    const float* __restrict__ W = (which == 0) ? Wq : ((which == 1) ? Wk : Wv);
    float* outp = (which == 0) ? g_q : ((which == 1) ? g_k : g_v);

    const int t  = threadIdx.x;
    const int ty = t >> 4;                  // 0..15 -> 8 rows each
    const int tx = t & 15;                  // 0..15 -> 4 cols each

    float acc[8][4];
    #pragma unroll
    for (int i = 0; i < 8; i++)
        #pragma unroll
        for (int j = 0; j < 4; j++) acc[i][j] = 0.0f;

    const float4* X4 = (const float4*)X;    // row stride 256 float4
    const float4* W4 = (const float4*)W;    // row stride 16 float4

    for (int kk = 0; kk < D_; kk += 16) {
        // Load A tile: 128 rows x 16 k (512 float4, 2 per thread), store transposed.
        #pragma unroll
        for (int r = 0; r < 2; r++) {
            int i   = t + r * 256;          // 0..511
            int row = i >> 2;               // 0..127
            int c4  = i & 3;                // 0..3 (float4 within 16 k's)
            float4 v = X4[(size_t)(mt * 128 + row) * 256 + (kk >> 2) + c4];
            As[c4 * 4 + 0][row] = v.x;
            As[c4 * 4 + 1][row] = v.y;
            As[c4 * 4 + 2][row] = v.z;
            As[c4 * 4 + 3][row] = v.w;
        }
        // Load B tile: 16 k x 64 n (256 float4, 1 per thread).
        {
            int row = t >> 4;               // 0..15 (k)
            int c4  = t & 15;               // 0..15 (n/4)
            float4 v = W4[(size_t)(kk + row) * 16 + c4];
            *(float4*)&Bs[row][c4 * 4] = v;
        }
        __syncthreads();

        #pragma unroll
        for (int k = 0; k < 16; k++) {
            float4 b  = *(const float4*)&Bs[k][tx * 4];
            float4 a0 = *(const float4*)&As[k][ty * 8];
            float4 a1 = *(const float4*)&As[k][ty * 8 + 4];
            float av[8] = {a0.x, a0.y, a0.z, a0.w, a1.x, a1.y, a1.z, a1.w};
            float bv[4] = {b.x, b.y, b.z, b.w};
            #pragma unroll
            for (int i = 0; i < 8; i++)
                #pragma unroll
                for (int j = 0; j < 4; j++)
                    acc[i][j] += av[i] * bv[j];
        }
        __syncthreads();
    }

    // Stage C into smem for row-wise LayerNorm stats.
    #pragma unroll
    for (int i = 0; i < 8; i++) {
        *(float4*)&Cs[ty * 8 + i][tx * 4] =
            make_float4(acc[i][0], acc[i][1], acc[i][2], acc[i][3]);
    }
    __syncthreads();

    if (t < 128) {
        float mu = 0.0f, rstd = 1.0f;
        if (which < 2) {
            float s = 0.0f;
            #pragma unroll
            for (int c = 0; c < 64; c++) s += Cs[t][c];
            mu = s * (1.0f / 64.0f);
            float vq = 0.0f;
            #pragma unroll
            for (int c = 0; c < 64; c++) {
                float d = Cs[t][c] - mu;
                vq += d * d;
            }
            rstd = rsqrtf(vq * (1.0f / 64.0f) + 1e-5f);
        }
        mu_s[t] = mu;
        rs_s[t] = rstd;
    }
    __syncthreads();

    float4* O4 = (float4*)outp;             // row stride 16 float4
    #pragma unroll
    for (int i = 0; i < 8; i++) {
        int row  = ty * 8 + i;
        float mu = mu_s[row];
        float rs = rs_s[row];
        float4 v = make_float4((acc[i][0] - mu) * rs, (acc[i][1] - mu) * rs,
                               (acc[i][2] - mu) * rs, (acc[i][3] - mu) * rs);
        O4[(size_t)(mt * 128 + row) * 16 + tx] = v;
    }
}

// ---------------------------------------------------------------------------
// Kernel 2: flash attention, thread-per-query.
// Grid: NROWS/128 blocks, 128 threads. Each thread owns one query row
// (q[64], o[64] in registers). 128-key tiles of K and V staged in dynamic
// smem (broadcast reads), scores buffered per-thread-row in smem so the
// online-softmax rescale happens once per tile.
// ---------------------------------------------------------------------------
#define KTILE 128
#define SPAD  129   // odd pad -> conflict-free per-thread score rows

__global__ __launch_bounds__(128) void attn_kernel(float* __restrict__ out)
{
    extern __shared__ float smem[];
    float4* Ks = (float4*)smem;                     // 128*16 float4 = 8192 f
    float4* Vs = (float4*)(smem + KTILE * H_);      // 8192 f
    float*  Sm = smem + 2 * KTILE * H_;             // 128*129 = 16512 f

    const int t     = threadIdx.x;
    const int qbase = blockIdx.x * 128;
    const int b     = qbase / S_;                   // 128 | 4096 -> same batch per block
    const int q_idx = qbase + t;

    const float4* gq4 = (const float4*)g_q;
    const float4* gk4 = (const float4*)g_k;
    const float4* gv4 = (const float4*)g_v;

    float4 q[16], o[16];
    #pragma unroll
    for (int i = 0; i < 16; i++) {
        q[i] = gq4[(size_t)q_idx * 16 + i];
        o[i] = make_float4(0.f, 0.f, 0.f, 0.f);
    }

    float m = -INFINITY, l = 0.0f;
    const float scale = 0.125f;                     // 1/sqrt(64)
    float* Srow = Sm + t * SPAD;

    for (int kt = 0; kt < S_ / KTILE; kt++) {
        const int kbase = b * S_ + kt * KTILE;

        // Cooperative coalesced load of K/V tiles (2048 float4 each).
        #pragma unroll
        for (int i = 0; i < 16; i++) {
            Ks[t + i * 128] = gk4[(size_t)kbase * 16 + t + i * 128];
            Vs[t + i * 128] = gv4[(size_t)kbase * 16 + t + i * 128];
        }
        __syncthreads();

        // Phase A: scores s_j = scale * (q . k_j), track tile max.
        float tmax = -INFINITY;
        for (int j0 = 0; j0 < KTILE; j0 += 8) {
            float s[8];
            #pragma unroll
            for (int jj = 0; jj < 8; jj++) s[jj] = 0.0f;
            #pragma unroll
            for (int d4 = 0; d4 < 16; d4++) {
                #pragma unroll
                for (int jj = 0; jj < 8; jj++) {
                    float4 kv = Ks[(j0 + jj) * 16 + d4];   // broadcast across warp
                    s[jj] += q[d4].x * kv.x;
                    s[jj] += q[d4].y * kv.y;
                    s[jj] += q[d4].z * kv.z;
                    s[jj] += q[d4].w * kv.w;
                }
            }
            #pragma unroll
            for (int jj = 0; jj < 8; jj++) {
                float sv = s[jj] * scale;
                Srow[j0 + jj] = sv;
                tmax = fmaxf(tmax, sv);
            }
        }

        // Phase B: online softmax update + P@V accumulate.
        float m_new = fmaxf(m, tmax);
        float corr  = __expf(m - m_new);
        l *= corr;
        #pragma unroll
        for (int i = 0; i < 16; i++) {
            o[i].x *= corr; o[i].y *= corr; o[i].z *= corr; o[i].w *= corr;
        }
        for (int j = 0; j < KTILE; j++) {
            float p = __expf(Srow[j] - m_new);
            l += p;
            #pragma unroll
            for (int d4 = 0; d4 < 16; d4++) {
                float4 vv = Vs[j * 16 + d4];               // broadcast across warp
                o[d4].x += p * vv.x;
                o[d4].y += p * vv.y;
                o[d4].z += p * vv.z;
                o[d4].w += p * vv.w;
            }
        }
        m = m_new;
        __syncthreads();
    }

    const float inv_l = 1.0f / l;
    float4* out4 = (float4*)out;
    #pragma unroll
    for (int i = 0; i < 16; i++) {
        out4[(size_t)q_idx * 16 + i] =
            make_float4(o[i].x * inv_l, o[i].y * inv_l, o[i].z * inv_l, o[i].w * inv_l);
    }
}

// ---------------------------------------------------------------------------
// Launch
// ---------------------------------------------------------------------------
extern "C" void kernel_launch(void* const* d_in, const int* in_sizes, int n_in,
                              void* d_out, int out_size)
{
    const float* X  = (const float*)d_in[0];
    const float* Wq = (const float*)d_in[1];
    const float* Wk = (const float*)d_in[2];
    const float* Wv = (const float*)d_in[3];
    float* out = (float*)d_out;

    dim3 gp(NROWS / 128, 3);
    proj_ln_kernel<<<gp, 256>>>(X, Wq, Wk, Wv);

    const int smem_bytes = (2 * KTILE * H_ + 128 * SPAD) * (int)sizeof(float); // 131584
    cudaFuncSetAttribute(attn_kernel, cudaFuncAttributeMaxDynamicSharedMemorySize, smem_bytes);
    attn_kernel<<<NROWS / 128, 128, smem_bytes>>>(out);
}

// round 3
// speedup vs baseline: 2.8494x; 2.8494x over previous
#include <cuda_runtime.h>
#include <cuda_bf16.h>
#include <math.h>
#include <stdint.h>

// Problem shape: B=4, S=4096, D=1024, H=64
#define B_ 4
#define S_ 4096
#define D_ 1024
#define H_ 64
#define NROWS (B_ * S_)   // 16384

// bf16 hi/lo split Q/K/V (Q pre-scaled by 1/sqrt(H)). Written by proj kernel.
__device__ __nv_bfloat16 g_qhi[NROWS * H_];
__device__ __nv_bfloat16 g_qlo[NROWS * H_];
__device__ __nv_bfloat16 g_khi[NROWS * H_];
__device__ __nv_bfloat16 g_klo[NROWS * H_];
__device__ __nv_bfloat16 g_vhi[NROWS * H_];
__device__ __nv_bfloat16 g_vlo[NROWS * H_];

// ===========================================================================
// helpers
// ===========================================================================
__device__ __forceinline__ uint32_t smem_u32(const void* p) {
    uint32_t a;
    asm("{ .reg .u64 t; cvta.to.shared.u64 t, %1; cvt.u32.u64 %0, t; }" : "=r"(a) : "l"(p));
    return a;
}
__device__ __forceinline__ uint32_t pack2(__nv_bfloat16 a, __nv_bfloat16 b) {
    return (uint32_t)__bfloat16_as_ushort(a) | ((uint32_t)__bfloat16_as_ushort(b) << 16);
}
// split (a,b) into bf16 hi pair and bf16 lo (residual) pair
__device__ __forceinline__ void split2(float a, float b, uint32_t& hi, uint32_t& lo) {
    __nv_bfloat16 ha = __float2bfloat16(a), hb = __float2bfloat16(b);
    hi = pack2(ha, hb);
    lo = pack2(__float2bfloat16(a - __bfloat162float(ha)),
               __float2bfloat16(b - __bfloat162float(hb)));
}

__device__ __forceinline__ void ldsm4(uint32_t& r0, uint32_t& r1, uint32_t& r2, uint32_t& r3, uint32_t addr) {
    asm volatile("ldmatrix.sync.aligned.m8n8.x4.shared.b16 {%0,%1,%2,%3}, [%4];"
        : "=r"(r0), "=r"(r1), "=r"(r2), "=r"(r3) : "r"(addr));
}
__device__ __forceinline__ void ldsm4t(uint32_t& r0, uint32_t& r1, uint32_t& r2, uint32_t& r3, uint32_t addr) {
    asm volatile("ldmatrix.sync.aligned.m8n8.x4.trans.shared.b16 {%0,%1,%2,%3}, [%4];"
        : "=r"(r0), "=r"(r1), "=r"(r2), "=r"(r3) : "r"(addr));
}
__device__ __forceinline__ void mma16816(float& d0, float& d1, float& d2, float& d3,
                                          uint32_t a0, uint32_t a1, uint32_t a2, uint32_t a3,
                                          uint32_t b0, uint32_t b1) {
    asm volatile("mma.sync.aligned.m16n8k16.row.col.f32.bf16.bf16.f32 "
        "{%0,%1,%2,%3}, {%4,%5,%6,%7}, {%8,%9}, {%0,%1,%2,%3};"
        : "+f"(d0), "+f"(d1), "+f"(d2), "+f"(d3)
        : "r"(a0), "r"(a1), "r"(a2), "r"(a3), "r"(b0), "r"(b1));
}

// ===========================================================================
// Kernel 1: fused QKV projection + LayerNorm; writes bf16 hi/lo splits.
// Grid (128, 3), block 256.
// ===========================================================================
__global__ __launch_bounds__(256) void proj_ln_kernel(
    const float* __restrict__ X, const float* __restrict__ Wq,
    const float* __restrict__ Wk, const float* __restrict__ Wv)
{
    __shared__ float As[16][132];
    __shared__ float Bs[16][64];
    __shared__ float Cs[128][68];
    __shared__ float mu_s[128];
    __shared__ float rs_s[128];

    const int mt    = blockIdx.x;
    const int which = blockIdx.y;
    const float* __restrict__ W = (which == 0) ? Wq : ((which == 1) ? Wk : Wv);

    const int t  = threadIdx.x;
    const int ty = t >> 4;
    const int tx = t & 15;

    float acc[8][4];
    #pragma unroll
    for (int i = 0; i < 8; i++)
        #pragma unroll
        for (int j = 0; j < 4; j++) acc[i][j] = 0.0f;

    const float4* X4 = (const float4*)X;
    const float4* W4 = (const float4*)W;

    for (int kk = 0; kk < D_; kk += 16) {
        #pragma unroll
        for (int r = 0; r < 2; r++) {
            int i = t + r * 256, row = i >> 2, c4 = i & 3;
            float4 v = X4[(size_t)(mt * 128 + row) * 256 + (kk >> 2) + c4];
            As[c4 * 4 + 0][row] = v.x; As[c4 * 4 + 1][row] = v.y;
            As[c4 * 4 + 2][row] = v.z; As[c4 * 4 + 3][row] = v.w;
        }
        {
            int row = t >> 4, c4 = t & 15;
            float4 v = W4[(size_t)(kk + row) * 16 + c4];
            *(float4*)&Bs[row][c4 * 4] = v;
        }
        __syncthreads();
        #pragma unroll
        for (int k = 0; k < 16; k++) {
            float4 b  = *(const float4*)&Bs[k][tx * 4];
            float4 a0 = *(const float4*)&As[k][ty * 8];
            float4 a1 = *(const float4*)&As[k][ty * 8 + 4];
            float av[8] = {a0.x, a0.y, a0.z, a0.w, a1.x, a1.y, a1.z, a1.w};
            float bv[4] = {b.x, b.y, b.z, b.w};
            #pragma unroll
            for (int i = 0; i < 8; i++)
                #pragma unroll
                for (int j = 0; j < 4; j++) acc[i][j] += av[i] * bv[j];
        }
        __syncthreads();
    }

    #pragma unroll
    for (int i = 0; i < 8; i++)
        *(float4*)&Cs[ty * 8 + i][tx * 4] = make_float4(acc[i][0], acc[i][1], acc[i][2], acc[i][3]);
    __syncthreads();

    if (t < 128) {
        float mu = 0.0f, rstd = 1.0f;
        if (which < 2) {
            float s = 0.0f;
            #pragma unroll
            for (int c = 0; c < 64; c++) s += Cs[t][c];
            mu = s * (1.0f / 64.0f);
            float vq = 0.0f;
            #pragma unroll
            for (int c = 0; c < 64; c++) { float d = Cs[t][c] - mu; vq += d * d; }
            rstd = rsqrtf(vq * (1.0f / 64.0f) + 1e-5f);
        }
        mu_s[t] = mu; rs_s[t] = rstd;
    }
    __syncthreads();

    __nv_bfloat16* ghi = (which == 0) ? g_qhi : ((which == 1) ? g_khi : g_vhi);
    __nv_bfloat16* glo = (which == 0) ? g_qlo : ((which == 1) ? g_klo : g_vlo);
    const float scale = (which == 0) ? 0.125f : 1.0f;   // fold 1/sqrt(64) into Q

    uint32_t* ghi32 = (uint32_t*)ghi;
    uint32_t* glo32 = (uint32_t*)glo;
    #pragma unroll
    for (int i = 0; i < 8; i++) {
        int row = ty * 8 + i;
        float mu = mu_s[row], rs = rs_s[row];
        float f0 = (acc[i][0] - mu) * rs * scale;
        float f1 = (acc[i][1] - mu) * rs * scale;
        float f2 = (acc[i][2] - mu) * rs * scale;
        float f3 = (acc[i][3] - mu) * rs * scale;
        uint32_t h0, l0, h1, l1;
        split2(f0, f1, h0, l0);
        split2(f2, f3, h1, l1);
        size_t idx2 = (size_t)(mt * 128 + row) * 32 + tx * 2;   // uint32 (bf16x2) index
        ghi32[idx2]     = h0; ghi32[idx2 + 1] = h1;
        glo32[idx2]     = l0; glo32[idx2 + 1] = l1;
    }
}

// ===========================================================================
// Kernel 2: flash attention with mma.sync.m16n8k16 bf16 (bf16x3 precision).
// Block = 256 threads (8 warps), each warp owns 16 query rows; 128 q/block.
// SMEM: Khi/Klo/Vhi/Vlo tiles [128 rows][64 bf16] = 16KB each, 64KB total.
// Swizzle: 16B chunk c of row r stored at r*128 + ((c ^ (r&7))<<4).
// ===========================================================================
#define OFF_KHI 0
#define OFF_KLO 16384
#define OFF_VHI 32768
#define OFF_VLO 49152
#define ATTN_SMEM 65536

__global__ __launch_bounds__(256) void attn_mma_kernel(float* __restrict__ out)
{
    extern __shared__ char smem[];
    const uint32_t sb = smem_u32(smem);
    const int tid  = threadIdx.x;
    const int warp = tid >> 5, lane = tid & 31;
    const int wrow = warp * 16;                       // warp's first query row in tile

    const int qbase = blockIdx.x * 128;
    const int b     = qbase / S_;

    // ---- stage Q tile (hi->KHI, lo->KLO), load A fragments, free the smem ----
    {
        const uint4* qh4 = (const uint4*)((const char*)g_qhi + (size_t)qbase * 128);
        const uint4* ql4 = (const uint4*)((const char*)g_qlo + (size_t)qbase * 128);
        #pragma unroll
        for (int j = 0; j < 4; j++) {
            int f = tid + j * 256;                    // 0..1023
            int r = f >> 3, c = f & 7;
            uint32_t so = r * 128 + ((c ^ (r & 7)) << 4);
            *(uint4*)(smem + OFF_KHI + so) = qh4[f];
            *(uint4*)(smem + OFF_KLO + so) = ql4[f];
        }
    }
    __syncthreads();

    uint32_t qh[4][4], ql[4][4];
    {
        int arow = wrow + (lane & 15);
        int s7   = arow & 7;
        #pragma unroll
        for (int kc = 0; kc < 4; kc++) {
            int c16 = 2 * kc + (lane >> 4);
            uint32_t ad = sb + OFF_KHI + arow * 128 + ((c16 ^ s7) << 4);
            ldsm4(qh[kc][0], qh[kc][1], qh[kc][2], qh[kc][3], ad);
            ldsm4(ql[kc][0], ql[kc][1], ql[kc][2], ql[kc][3], ad + (OFF_KLO - OFF_KHI));
        }
    }

    // accumulators
    float s0[16], s1[16], s2[16], s3[16];
    float o0[8], o1[8], o2[8], o3[8];
    #pragma unroll
    for (int i = 0; i < 8; i++) { o0[i] = 0.f; o1[i] = 0.f; o2[i] = 0.f; o3[i] = 0.f; }
    float m0 = -INFINITY, m1 = -INFINITY, l0 = 0.f, l1 = 0.f;

    // lane constants for B-fragment ldmatrix addressing
    const int s7   = lane & 7;
    const int krq  = (lane & 7) + ((lane >> 4) << 3);  // QK: row within 16-key window
    const int cbit = (lane >> 3) & 1;                  // QK: dim-half select
    const int krv  = lane & 15;                        // PV: key row within 16-key chunk
    const int vbit = lane >> 4;                        // PV: h-chunk select

    for (int kt = 0; kt < S_ / 128; kt++) {
        const int kbase = b * S_ + kt * 128;
        __syncthreads();                               // all warps done reading prev tile

        // ---- cooperative tile load: 64KB (khi/klo/vhi/vlo), swizzled ----
        {
            const uint4* kh4 = (const uint4*)((const char*)g_khi + (size_t)kbase * 128);
            const uint4* kl4 = (const uint4*)((const char*)g_klo + (size_t)kbase * 128);
            const uint4* vh4 = (const uint4*)((const char*)g_vhi + (size_t)kbase * 128);
            const uint4* vl4 = (const uint4*)((const char*)g_vlo + (size_t)kbase * 128);
            #pragma unroll
            for (int j = 0; j < 4; j++) {
                int f = tid + j * 256;
                int r = f >> 3, c = f & 7;
                uint32_t so = r * 128 + ((c ^ (r & 7)) << 4);
                *(uint4*)(smem + OFF_KHI + so) = kh4[f];
                *(uint4*)(smem + OFF_KLO + so) = kl4[f];
                *(uint4*)(smem + OFF_VHI + so) = vh4[f];
                *(uint4*)(smem + OFF_VLO + so) = vl4[f];
            }
        }
        __syncthreads();

        // ---- S = Q K^T (bf16x3) ----
        #pragma unroll
        for (int i = 0; i < 16; i++) { s0[i] = 0.f; s1[i] = 0.f; s2[i] = 0.f; s3[i] = 0.f; }
        #pragma unroll
        for (int kc = 0; kc < 4; kc++) {
            #pragma unroll
            for (int ncp = 0; ncp < 8; ncp++) {
                uint32_t ad = sb + OFF_KHI + (uint32_t)(ncp * 16 + krq) * 128
                            + (((2 * kc + cbit) ^ s7) << 4);
                uint32_t bh0, bh1, bh2, bh3, bl0, bl1, bl2, bl3;
                ldsm4(bh0, bh1, bh2, bh3, ad);
                ldsm4(bl0, bl1, bl2, bl3, ad + (OFF_KLO - OFF_KHI));
                int n = 2 * ncp;
                mma16816(s0[n], s1[n], s2[n], s3[n], qh[kc][0], qh[kc][1], qh[kc][2], qh[kc][3], bh0, bh1);
                mma16816(s0[n], s1[n], s2[n], s3[n], ql[kc][0], ql[kc][1], ql[kc][2], ql[kc][3], bh0, bh1);
                mma16816(s0[n], s1[n], s2[n], s3[n], qh[kc][0], qh[kc][1], qh[kc][2], qh[kc][3], bl0, bl1);
                mma16816(s0[n+1], s1[n+1], s2[n+1], s3[n+1], qh[kc][0], qh[kc][1], qh[kc][2], qh[kc][3], bh2, bh3);
                mma16816(s0[n+1], s1[n+1], s2[n+1], s3[n+1], ql[kc][0], ql[kc][1], ql[kc][2], ql[kc][3], bh2, bh3);
                mma16816(s0[n+1], s1[n+1], s2[n+1], s3[n+1], qh[kc][0], qh[kc][1], qh[kc][2], qh[kc][3], bl2, bl3);
            }
        }

        // ---- online softmax (rows r=lane/4 and r+8; reduce across 4-lane group) ----
        float tmax0 = -INFINITY, tmax1 = -INFINITY;
        #pragma unroll
        for (int i = 0; i < 16; i++) {
            tmax0 = fmaxf(tmax0, fmaxf(s0[i], s1[i]));
            tmax1 = fmaxf(tmax1, fmaxf(s2[i], s3[i]));
        }
        tmax0 = fmaxf(tmax0, __shfl_xor_sync(0xffffffffu, tmax0, 1));
        tmax0 = fmaxf(tmax0, __shfl_xor_sync(0xffffffffu, tmax0, 2));
        tmax1 = fmaxf(tmax1, __shfl_xor_sync(0xffffffffu, tmax1, 1));
        tmax1 = fmaxf(tmax1, __shfl_xor_sync(0xffffffffu, tmax1, 2));

        float mn0 = fmaxf(m0, tmax0), mn1 = fmaxf(m1, tmax1);
        float corr0 = __expf(m0 - mn0), corr1 = __expf(m1 - mn1);

        float sum0 = 0.f, sum1 = 0.f;
        #pragma unroll
        for (int i = 0; i < 16; i++) {
            s0[i] = __expf(s0[i] - mn0); s1[i] = __expf(s1[i] - mn0);
            s2[i] = __expf(s2[i] - mn1); s3[i] = __expf(s3[i] - mn1);
            sum0 += s0[i] + s1[i];
            sum1 += s2[i] + s3[i];
        }
        sum0 += __shfl_xor_sync(0xffffffffu, sum0, 1);
        sum0 += __shfl_xor_sync(0xffffffffu, sum0, 2);
        sum1 += __shfl_xor_sync(0xffffffffu, sum1, 1);
        sum1 += __shfl_xor_sync(0xffffffffu, sum1, 2);

        l0 = l0 * corr0 + sum0;  m0 = mn0;
        l1 = l1 * corr1 + sum1;  m1 = mn1;
        #pragma unroll
        for (int i = 0; i < 8; i++) {
            o0[i] *= corr0; o1[i] *= corr0;
            o2[i] *= corr1; o3[i] *= corr1;
        }

        // ---- O += P V (bf16x3) ----
        #pragma unroll
        for (int kc = 0; kc < 8; kc++) {
            uint32_t ph0, ph1, ph2, ph3, pl0, pl1, pl2, pl3;
            split2(s0[2*kc],   s1[2*kc],   ph0, pl0);
            split2(s2[2*kc],   s3[2*kc],   ph1, pl1);
            split2(s0[2*kc+1], s1[2*kc+1], ph2, pl2);
            split2(s2[2*kc+1], s3[2*kc+1], ph3, pl3);
            #pragma unroll
            for (int ncp = 0; ncp < 4; ncp++) {
                uint32_t ad = sb + OFF_VHI + (uint32_t)(kc * 16 + krv) * 128
                            + (((2 * ncp + vbit) ^ s7) << 4);
                uint32_t bh0, bh1, bh2, bh3, bl0, bl1, bl2, bl3;
                ldsm4t(bh0, bh1, bh2, bh3, ad);
                ldsm4t(bl0, bl1, bl2, bl3, ad + (OFF_VLO - OFF_VHI));
                int n = 2 * ncp;
                mma16816(o0[n], o1[n], o2[n], o3[n], ph0, ph1, ph2, ph3, bh0, bh1);
                mma16816(o0[n], o1[n], o2[n], o3[n], pl0, pl1, pl2, pl3, bh0, bh1);
                mma16816(o0[n], o1[n], o2[n], o3[n], ph0, ph1, ph2, ph3, bl0, bl1);
                mma16816(o0[n+1], o1[n+1], o2[n+1], o3[n+1], ph0, ph1, ph2, ph3, bh2, bh3);
                mma16816(o0[n+1], o1[n+1], o2[n+1], o3[n+1], pl0, pl1, pl2, pl3, bh2, bh3);
                mma16816(o0[n+1], o1[n+1], o2[n+1], o3[n+1], ph0, ph1, ph2, ph3, bl2, bl3);
            }
        }
    }

    // ---- epilogue ----
    const float il0 = 1.0f / l0, il1 = 1.0f / l1;
    const int r  = lane >> 2;
    const int c2 = (lane & 3) * 2;
    float2* out2 = (float2*)out;
    #pragma unroll
    for (int nc = 0; nc < 8; nc++) {
        size_t i_lo = ((size_t)(qbase + wrow + r)     * 64 + 8 * nc + c2) >> 1;
        size_t i_hi = ((size_t)(qbase + wrow + r + 8) * 64 + 8 * nc + c2) >> 1;
        out2[i_lo] = make_float2(o0[nc] * il0, o1[nc] * il0);
        out2[i_hi] = make_float2(o2[nc] * il1, o3[nc] * il1);
    }
}

// ===========================================================================
// Launch
// ===========================================================================
extern "C" void kernel_launch(void* const* d_in, const int* in_sizes, int n_in,
                              void* d_out, int out_size)
{
    const float* X  = (const float*)d_in[0];
    const float* Wq = (const float*)d_in[1];
    const float* Wk = (const float*)d_in[2];
    const float* Wv = (const float*)d_in[3];
    float* out = (float*)d_out;

    dim3 gp(NROWS / 128, 3);
    proj_ln_kernel<<<gp, 256>>>(X, Wq, Wk, Wv);

    cudaFuncSetAttribute(attn_mma_kernel, cudaFuncAttributeMaxDynamicSharedMemorySize, ATTN_SMEM);
    attn_mma_kernel<<<NROWS / 128, 256, ATTN_SMEM>>>(out);
}

// round 4
// speedup vs baseline: 4.3237x; 1.5174x over previous
#include <cuda_runtime.h>
#include <cuda_bf16.h>
#include <math.h>
#include <stdint.h>

// Problem shape: B=4, S=4096, D=1024, H=64
#define B_ 4
#define S_ 4096
#define D_ 1024
#define H_ 64
#define NROWS (B_ * S_)   // 16384

// bf16 hi/lo split Q/K/V (Q pre-scaled by 1/sqrt(H)). Written by proj kernel.
__device__ __nv_bfloat16 g_qhi[NROWS * H_];
__device__ __nv_bfloat16 g_qlo[NROWS * H_];
__device__ __nv_bfloat16 g_khi[NROWS * H_];
__device__ __nv_bfloat16 g_klo[NROWS * H_];
__device__ __nv_bfloat16 g_vhi[NROWS * H_];
__device__ __nv_bfloat16 g_vlo[NROWS * H_];

// ===========================================================================
// helpers
// ===========================================================================
__device__ __forceinline__ uint32_t smem_u32(const void* p) {
    uint32_t a;
    asm("{ .reg .u64 t; cvta.to.shared.u64 t, %1; cvt.u32.u64 %0, t; }" : "=r"(a) : "l"(p));
    return a;
}
__device__ __forceinline__ uint32_t pack2(__nv_bfloat16 a, __nv_bfloat16 b) {
    return (uint32_t)__bfloat16_as_ushort(a) | ((uint32_t)__bfloat16_as_ushort(b) << 16);
}
__device__ __forceinline__ void split2(float a, float b, uint32_t& hi, uint32_t& lo) {
    __nv_bfloat16 ha = __float2bfloat16(a), hb = __float2bfloat16(b);
    hi = pack2(ha, hb);
    lo = pack2(__float2bfloat16(a - __bfloat162float(ha)),
               __float2bfloat16(b - __bfloat162float(hb)));
}

__device__ __forceinline__ void ldsm4(uint32_t& r0, uint32_t& r1, uint32_t& r2, uint32_t& r3, uint32_t addr) {
    asm volatile("ldmatrix.sync.aligned.m8n8.x4.shared.b16 {%0,%1,%2,%3}, [%4];"
        : "=r"(r0), "=r"(r1), "=r"(r2), "=r"(r3) : "r"(addr));
}
__device__ __forceinline__ void ldsm4t(uint32_t& r0, uint32_t& r1, uint32_t& r2, uint32_t& r3, uint32_t addr) {
    asm volatile("ldmatrix.sync.aligned.m8n8.x4.trans.shared.b16 {%0,%1,%2,%3}, [%4];"
        : "=r"(r0), "=r"(r1), "=r"(r2), "=r"(r3) : "r"(addr));
}
__device__ __forceinline__ void mma16816(float& d0, float& d1, float& d2, float& d3,
                                          uint32_t a0, uint32_t a1, uint32_t a2, uint32_t a3,
                                          uint32_t b0, uint32_t b1) {
    asm volatile("mma.sync.aligned.m16n8k16.row.col.f32.bf16.bf16.f32 "
        "{%0,%1,%2,%3}, {%4,%5,%6,%7}, {%8,%9}, {%0,%1,%2,%3};"
        : "+f"(d0), "+f"(d1), "+f"(d2), "+f"(d3)
        : "r"(a0), "r"(a1), "r"(a2), "r"(a3), "r"(b0), "r"(b1));
}

// ===========================================================================
// Kernel 1: fused QKV projection + LayerNorm via mma.sync bf16x3.
// Grid = 128 row-tiles, block = 256 (8 warps, 16 rows each).
// Per k-chunk (64): stage X[128x64] and Wq/Wk/Wv[64x64] as bf16 hi/lo in smem.
// SMEM: Xhi/Xlo 16KB each, 6 W buffers 8KB each -> 80KB.
// ===========================================================================
#define P_XHI 0
#define P_XLO 16384
#define P_W0H 32768           // Wq hi
#define P_WSTRIDE 8192        // [W0H, W0L, W1H, W1L, W2H, W2L]
#define PROJ_SMEM (32768 + 6 * 8192)

__global__ __launch_bounds__(256) void proj_ln_kernel(
    const float* __restrict__ X, const float* __restrict__ Wq,
    const float* __restrict__ Wk, const float* __restrict__ Wv)
{
    extern __shared__ char smem[];
    const uint32_t sb = smem_u32(smem);
    const int tid  = threadIdx.x;
    const int warp = tid >> 5, lane = tid & 31;
    const int wrow = warp * 16;
    const int mt   = blockIdx.x;

    const float* Ws[3] = {Wq, Wk, Wv};

    // accumulators: [matrix][ncol-pair]; rows rA = lane>>2, rB = rA+8; cols 8nc+(lane&3)*2(+1)
    float a0[3][8], a1[3][8], a2[3][8], a3[3][8];
    #pragma unroll
    for (int m = 0; m < 3; m++)
        #pragma unroll
        for (int nc = 0; nc < 8; nc++) { a0[m][nc]=0.f; a1[m][nc]=0.f; a2[m][nc]=0.f; a3[m][nc]=0.f; }

    const float4* X4 = (const float4*)X;

    // lane constants
    const int arow = wrow + (lane & 15);
    const int as7  = arow & 7;
    const int abit = lane >> 4;
    const int krv  = lane & 15;
    const int vbit = lane >> 4;
    const int s7   = lane & 7;

    for (int kk = 0; kk < D_; kk += 64) {
        __syncthreads();   // previous iter's ldsm done

        // ---- stage X chunk [128 rows][64 k] -> bf16 hi/lo, swizzled 128B rows ----
        #pragma unroll
        for (int j = 0; j < 8; j++) {
            int f = tid + j * 256;                  // 0..2047
            int r = f >> 4, c4 = f & 15;
            float4 v = X4[(size_t)(mt * 128 + r) * 256 + (kk >> 2) + c4];
            uint32_t h0, l0, h1, l1;
            split2(v.x, v.y, h0, l0);
            split2(v.z, v.w, h1, l1);
            uint32_t so = (uint32_t)(r * 128 + (((c4 >> 1) ^ (r & 7)) << 4) + (c4 & 1) * 8);
            *(uint32_t*)(smem + P_XHI + so)     = h0;
            *(uint32_t*)(smem + P_XHI + so + 4) = h1;
            *(uint32_t*)(smem + P_XLO + so)     = l0;
            *(uint32_t*)(smem + P_XLO + so + 4) = l1;
        }
        // ---- stage W chunks [64 k][64 n] x3 -> bf16 hi/lo ----
        #pragma unroll
        for (int m = 0; m < 3; m++) {
            const float4* W4 = (const float4*)Ws[m];
            #pragma unroll
            for (int j = 0; j < 4; j++) {
                int f = tid + j * 256;              // 0..1023
                int r = f >> 4, c4 = f & 15;
                float4 v = W4[(size_t)(kk + r) * 16 + c4];
                uint32_t h0, l0, h1, l1;
                split2(v.x, v.y, h0, l0);
                split2(v.z, v.w, h1, l1);
                uint32_t so = (uint32_t)(r * 128 + (((c4 >> 1) ^ (r & 7)) << 4) + (c4 & 1) * 8);
                *(uint32_t*)(smem + P_W0H + m * 2 * P_WSTRIDE + so)              = h0;
                *(uint32_t*)(smem + P_W0H + m * 2 * P_WSTRIDE + so + 4)          = h1;
                *(uint32_t*)(smem + P_W0H + (m * 2 + 1) * P_WSTRIDE + so)        = l0;
                *(uint32_t*)(smem + P_W0H + (m * 2 + 1) * P_WSTRIDE + so + 4)    = l1;
            }
        }
        __syncthreads();

        // ---- A fragments (X rows) ----
        uint32_t xh[4][4], xl[4][4];
        #pragma unroll
        for (int kc = 0; kc < 4; kc++) {
            int c16 = 2 * kc + abit;
            uint32_t ad = sb + P_XHI + (uint32_t)(arow * 128) + ((c16 ^ as7) << 4);
            ldsm4(xh[kc][0], xh[kc][1], xh[kc][2], xh[kc][3], ad);
            ldsm4(xl[kc][0], xl[kc][1], xl[kc][2], xl[kc][3], ad + (P_XLO - P_XHI));
        }

        // ---- 3 GEMMs, bf16x3 ----
        #pragma unroll
        for (int m = 0; m < 3; m++) {
            uint32_t wbase = sb + P_W0H + (uint32_t)(m * 2 * P_WSTRIDE);
            #pragma unroll
            for (int kc = 0; kc < 4; kc++) {
                #pragma unroll
                for (int ncp = 0; ncp < 4; ncp++) {
                    uint32_t ad = wbase + (uint32_t)((kc * 16 + krv) * 128)
                                + (((2 * ncp + vbit) ^ s7) << 4);
                    uint32_t bh0, bh1, bh2, bh3, bl0, bl1, bl2, bl3;
                    ldsm4t(bh0, bh1, bh2, bh3, ad);
                    ldsm4t(bl0, bl1, bl2, bl3, ad + P_WSTRIDE);
                    int n = 2 * ncp;
                    mma16816(a0[m][n], a1[m][n], a2[m][n], a3[m][n],
                             xh[kc][0], xh[kc][1], xh[kc][2], xh[kc][3], bh0, bh1);
                    mma16816(a0[m][n], a1[m][n], a2[m][n], a3[m][n],
                             xl[kc][0], xl[kc][1], xl[kc][2], xl[kc][3], bh0, bh1);
                    mma16816(a0[m][n], a1[m][n], a2[m][n], a3[m][n],
                             xh[kc][0], xh[kc][1], xh[kc][2], xh[kc][3], bl0, bl1);
                    mma16816(a0[m][n+1], a1[m][n+1], a2[m][n+1], a3[m][n+1],
                             xh[kc][0], xh[kc][1], xh[kc][2], xh[kc][3], bh2, bh3);
                    mma16816(a0[m][n+1], a1[m][n+1], a2[m][n+1], a3[m][n+1],
                             xl[kc][0], xl[kc][1], xl[kc][2], xl[kc][3], bh2, bh3);
                    mma16816(a0[m][n+1], a1[m][n+1], a2[m][n+1], a3[m][n+1],
                             xh[kc][0], xh[kc][1], xh[kc][2], xh[kc][3], bl2, bl3);
                }
            }
        }
    }

    // ---- epilogue: LayerNorm (Q,K) in registers + quad shuffles, split + store ----
    const int rA = mt * 128 + wrow + (lane >> 2);
    const int rB = rA + 8;

    #pragma unroll
    for (int m = 0; m < 3; m++) {
        float mu0 = 0.f, mu1 = 0.f, rs0 = 1.f, rs1 = 1.f;
        if (m < 2) {
            float sum0 = 0.f, sum1 = 0.f;
            #pragma unroll
            for (int nc = 0; nc < 8; nc++) {
                sum0 += a0[m][nc] + a1[m][nc];
                sum1 += a2[m][nc] + a3[m][nc];
            }
            sum0 += __shfl_xor_sync(0xffffffffu, sum0, 1);
            sum0 += __shfl_xor_sync(0xffffffffu, sum0, 2);
            sum1 += __shfl_xor_sync(0xffffffffu, sum1, 1);
            sum1 += __shfl_xor_sync(0xffffffffu, sum1, 2);
            mu0 = sum0 * (1.0f / 64.0f);
            mu1 = sum1 * (1.0f / 64.0f);
            float v0 = 0.f, v1 = 0.f;
            #pragma unroll
            for (int nc = 0; nc < 8; nc++) {
                float d00 = a0[m][nc] - mu0, d01 = a1[m][nc] - mu0;
                float d10 = a2[m][nc] - mu1, d11 = a3[m][nc] - mu1;
                v0 += d00 * d00 + d01 * d01;
                v1 += d10 * d10 + d11 * d11;
            }
            v0 += __shfl_xor_sync(0xffffffffu, v0, 1);
            v0 += __shfl_xor_sync(0xffffffffu, v0, 2);
            v1 += __shfl_xor_sync(0xffffffffu, v1, 1);
            v1 += __shfl_xor_sync(0xffffffffu, v1, 2);
            rs0 = rsqrtf(v0 * (1.0f / 64.0f) + 1e-5f);
            rs1 = rsqrtf(v1 * (1.0f / 64.0f) + 1e-5f);
        }
        const float sc = (m == 0) ? 0.125f : 1.0f;   // fold 1/sqrt(64) into Q
        rs0 *= sc; rs1 *= sc;

        uint32_t* ghi32 = (uint32_t*)((m == 0) ? g_qhi : ((m == 1) ? g_khi : g_vhi));
        uint32_t* glo32 = (uint32_t*)((m == 0) ? g_qlo : ((m == 1) ? g_klo : g_vlo));

        #pragma unroll
        for (int nc = 0; nc < 8; nc++) {
            uint32_t hA, lA, hB, lB;
            split2((a0[m][nc] - mu0) * rs0, (a1[m][nc] - mu0) * rs0, hA, lA);
            split2((a2[m][nc] - mu1) * rs1, (a3[m][nc] - mu1) * rs1, hB, lB);
            size_t iA = (size_t)rA * 32 + nc * 4 + (lane & 3);
            size_t iB = (size_t)rB * 32 + nc * 4 + (lane & 3);
            ghi32[iA] = hA; glo32[iA] = lA;
            ghi32[iB] = hB; glo32[iB] = lB;
        }
    }
}

// ===========================================================================
// Kernel 2: flash attention with mma.sync.m16n8k16 bf16 (bf16x3 precision).
// (unchanged from R3: 385.5us total, attn 175us, tensor=48.6%)
// ===========================================================================
#define OFF_KHI 0
#define OFF_KLO 16384
#define OFF_VHI 32768
#define OFF_VLO 49152
#define ATTN_SMEM 65536

__global__ __launch_bounds__(256) void attn_mma_kernel(float* __restrict__ out)
{
    extern __shared__ char smem[];
    const uint32_t sb = smem_u32(smem);
    const int tid  = threadIdx.x;
    const int warp = tid >> 5, lane = tid & 31;
    const int wrow = warp * 16;

    const int qbase = blockIdx.x * 128;
    const int b     = qbase / S_;

    {
        const uint4* qh4 = (const uint4*)((const char*)g_qhi + (size_t)qbase * 128);
        const uint4* ql4 = (const uint4*)((const char*)g_qlo + (size_t)qbase * 128);
        #pragma unroll
        for (int j = 0; j < 4; j++) {
            int f = tid + j * 256;
            int r = f >> 3, c = f & 7;
            uint32_t so = r * 128 + ((c ^ (r & 7)) << 4);
            *(uint4*)(smem + OFF_KHI + so) = qh4[f];
            *(uint4*)(smem + OFF_KLO + so) = ql4[f];
        }
    }
    __syncthreads();

    uint32_t qh[4][4], ql[4][4];
    {
        int arow = wrow + (lane & 15);
        int s7   = arow & 7;
        #pragma unroll
        for (int kc = 0; kc < 4; kc++) {
            int c16 = 2 * kc + (lane >> 4);
            uint32_t ad = sb + OFF_KHI + arow * 128 + ((c16 ^ s7) << 4);
            ldsm4(qh[kc][0], qh[kc][1], qh[kc][2], qh[kc][3], ad);
            ldsm4(ql[kc][0], ql[kc][1], ql[kc][2], ql[kc][3], ad + (OFF_KLO - OFF_KHI));
        }
    }

    float s0[16], s1[16], s2[16], s3[16];
    float o0[8], o1[8], o2[8], o3[8];
    #pragma unroll
    for (int i = 0; i < 8; i++) { o0[i] = 0.f; o1[i] = 0.f; o2[i] = 0.f; o3[i] = 0.f; }
    float m0 = -INFINITY, m1 = -INFINITY, l0 = 0.f, l1 = 0.f;

    const int s7   = lane & 7;
    const int krq  = (lane & 7) + ((lane >> 4) << 3);
    const int cbit = (lane >> 3) & 1;
    const int krv  = lane & 15;
    const int vbit = lane >> 4;

    for (int kt = 0; kt < S_ / 128; kt++) {
        const int kbase = b * S_ + kt * 128;
        __syncthreads();

        {
            const uint4* kh4 = (const uint4*)((const char*)g_khi + (size_t)kbase * 128);
            const uint4* kl4 = (const uint4*)((const char*)g_klo + (size_t)kbase * 128);
            const uint4* vh4 = (const uint4*)((const char*)g_vhi + (size_t)kbase * 128);
            const uint4* vl4 = (const uint4*)((const char*)g_vlo + (size_t)kbase * 128);
            #pragma unroll
            for (int j = 0; j < 4; j++) {
                int f = tid + j * 256;
                int r = f >> 3, c = f & 7;
                uint32_t so = r * 128 + ((c ^ (r & 7)) << 4);
                *(uint4*)(smem + OFF_KHI + so) = kh4[f];
                *(uint4*)(smem + OFF_KLO + so) = kl4[f];
                *(uint4*)(smem + OFF_VHI + so) = vh4[f];
                *(uint4*)(smem + OFF_VLO + so) = vl4[f];
            }
        }
        __syncthreads();

        #pragma unroll
        for (int i = 0; i < 16; i++) { s0[i] = 0.f; s1[i] = 0.f; s2[i] = 0.f; s3[i] = 0.f; }
        #pragma unroll
        for (int kc = 0; kc < 4; kc++) {
            #pragma unroll
            for (int ncp = 0; ncp < 8; ncp++) {
                uint32_t ad = sb + OFF_KHI + (uint32_t)(ncp * 16 + krq) * 128
                            + (((2 * kc + cbit) ^ s7) << 4);
                uint32_t bh0, bh1, bh2, bh3, bl0, bl1, bl2, bl3;
                ldsm4(bh0, bh1, bh2, bh3, ad);
                ldsm4(bl0, bl1, bl2, bl3, ad + (OFF_KLO - OFF_KHI));
                int n = 2 * ncp;
                mma16816(s0[n], s1[n], s2[n], s3[n], qh[kc][0], qh[kc][1], qh[kc][2], qh[kc][3], bh0, bh1);
                mma16816(s0[n], s1[n], s2[n], s3[n], ql[kc][0], ql[kc][1], ql[kc][2], ql[kc][3], bh0, bh1);
                mma16816(s0[n], s1[n], s2[n], s3[n], qh[kc][0], qh[kc][1], qh[kc][2], qh[kc][3], bl0, bl1);
                mma16816(s0[n+1], s1[n+1], s2[n+1], s3[n+1], qh[kc][0], qh[kc][1], qh[kc][2], qh[kc][3], bh2, bh3);
                mma16816(s0[n+1], s1[n+1], s2[n+1], s3[n+1], ql[kc][0], ql[kc][1], ql[kc][2], ql[kc][3], bh2, bh3);
                mma16816(s0[n+1], s1[n+1], s2[n+1], s3[n+1], qh[kc][0], qh[kc][1], qh[kc][2], qh[kc][3], bl2, bl3);
            }
        }

        float tmax0 = -INFINITY, tmax1 = -INFINITY;
        #pragma unroll
        for (int i = 0; i < 16; i++) {
            tmax0 = fmaxf(tmax0, fmaxf(s0[i], s1[i]));
            tmax1 = fmaxf(tmax1, fmaxf(s2[i], s3[i]));
        }
        tmax0 = fmaxf(tmax0, __shfl_xor_sync(0xffffffffu, tmax0, 1));
        tmax0 = fmaxf(tmax0, __shfl_xor_sync(0xffffffffu, tmax0, 2));
        tmax1 = fmaxf(tmax1, __shfl_xor_sync(0xffffffffu, tmax1, 1));
        tmax1 = fmaxf(tmax1, __shfl_xor_sync(0xffffffffu, tmax1, 2));

        float mn0 = fmaxf(m0, tmax0), mn1 = fmaxf(m1, tmax1);
        float corr0 = __expf(m0 - mn0), corr1 = __expf(m1 - mn1);

        float sum0 = 0.f, sum1 = 0.f;
        #pragma unroll
        for (int i = 0; i < 16; i++) {
            s0[i] = __expf(s0[i] - mn0); s1[i] = __expf(s1[i] - mn0);
            s2[i] = __expf(s2[i] - mn1); s3[i] = __expf(s3[i] - mn1);
            sum0 += s0[i] + s1[i];
            sum1 += s2[i] + s3[i];
        }
        sum0 += __shfl_xor_sync(0xffffffffu, sum0, 1);
        sum0 += __shfl_xor_sync(0xffffffffu, sum0, 2);
        sum1 += __shfl_xor_sync(0xffffffffu, sum1, 1);
        sum1 += __shfl_xor_sync(0xffffffffu, sum1, 2);

        l0 = l0 * corr0 + sum0;  m0 = mn0;
        l1 = l1 * corr1 + sum1;  m1 = mn1;
        #pragma unroll
        for (int i = 0; i < 8; i++) {
            o0[i] *= corr0; o1[i] *= corr0;
            o2[i] *= corr1; o3[i] *= corr1;
        }

        #pragma unroll
        for (int kc = 0; kc < 8; kc++) {
            uint32_t ph0, ph1, ph2, ph3, pl0, pl1, pl2, pl3;
            split2(s0[2*kc],   s1[2*kc],   ph0, pl0);
            split2(s2[2*kc],   s3[2*kc],   ph1, pl1);
            split2(s0[2*kc+1], s1[2*kc+1], ph2, pl2);
            split2(s2[2*kc+1], s3[2*kc+1], ph3, pl3);
            #pragma unroll
            for (int ncp = 0; ncp < 4; ncp++) {
                uint32_t ad = sb + OFF_VHI + (uint32_t)(kc * 16 + krv) * 128
                            + (((2 * ncp + vbit) ^ s7) << 4);
                uint32_t bh0, bh1, bh2, bh3, bl0, bl1, bl2, bl3;
                ldsm4t(bh0, bh1, bh2, bh3, ad);
                ldsm4t(bl0, bl1, bl2, bl3, ad + (OFF_VLO - OFF_VHI));
                int n = 2 * ncp;
                mma16816(o0[n], o1[n], o2[n], o3[n], ph0, ph1, ph2, ph3, bh0, bh1);
                mma16816(o0[n], o1[n], o2[n], o3[n], pl0, pl1, pl2, pl3, bh0, bh1);
                mma16816(o0[n], o1[n], o2[n], o3[n], ph0, ph1, ph2, ph3, bl0, bl1);
                mma16816(o0[n+1], o1[n+1], o2[n+1], o3[n+1], ph0, ph1, ph2, ph3, bh2, bh3);
                mma16816(o0[n+1], o1[n+1], o2[n+1], o3[n+1], pl0, pl1, pl2, pl3, bh2, bh3);
                mma16816(o0[n+1], o1[n+1], o2[n+1], o3[n+1], ph0, ph1, ph2, ph3, bl2, bl3);
            }
        }
    }

    const float il0 = 1.0f / l0, il1 = 1.0f / l1;
    const int r  = lane >> 2;
    const int c2 = (lane & 3) * 2;
    float2* out2 = (float2*)out;
    #pragma unroll
    for (int nc = 0; nc < 8; nc++) {
        size_t i_lo = ((size_t)(qbase + wrow + r)     * 64 + 8 * nc + c2) >> 1;
        size_t i_hi = ((size_t)(qbase + wrow + r + 8) * 64 + 8 * nc + c2) >> 1;
        out2[i_lo] = make_float2(o0[nc] * il0, o1[nc] * il0);
        out2[i_hi] = make_float2(o2[nc] * il1, o3[nc] * il1);
    }
}

// ===========================================================================
// Launch
// ===========================================================================
extern "C" void kernel_launch(void* const* d_in, const int* in_sizes, int n_in,
                              void* d_out, int out_size)
{
    const float* X  = (const float*)d_in[0];
    const float* Wq = (const float*)d_in[1];
    const float* Wk = (const float*)d_in[2];
    const float* Wv = (const float*)d_in[3];
    float* out = (float*)d_out;

    cudaFuncSetAttribute(proj_ln_kernel, cudaFuncAttributeMaxDynamicSharedMemorySize, PROJ_SMEM);
    proj_ln_kernel<<<NROWS / 128, 256, PROJ_SMEM>>>(X, Wq, Wk, Wv);

    cudaFuncSetAttribute(attn_mma_kernel, cudaFuncAttributeMaxDynamicSharedMemorySize, ATTN_SMEM);
    attn_mma_kernel<<<NROWS / 128, 256, ATTN_SMEM>>>(out);
}

// round 5
// speedup vs baseline: 4.7450x; 1.0974x over previous
#include <cuda_runtime.h>
#include <cuda_bf16.h>
#include <math.h>
#include <stdint.h>

// Problem shape: B=4, S=4096, D=1024, H=64
#define B_ 4
#define S_ 4096
#define D_ 1024
#define H_ 64
#define NROWS (B_ * S_)   // 16384

// bf16 hi/lo split Q/K/V (Q pre-scaled by 1/sqrt(H)). Written by proj kernel.
__device__ __nv_bfloat16 g_qhi[NROWS * H_];
__device__ __nv_bfloat16 g_qlo[NROWS * H_];
__device__ __nv_bfloat16 g_khi[NROWS * H_];
__device__ __nv_bfloat16 g_klo[NROWS * H_];
__device__ __nv_bfloat16 g_vhi[NROWS * H_];
__device__ __nv_bfloat16 g_vlo[NROWS * H_];
// Pre-split W (bf16 hi/lo) in per-64k-chunk swizzled tile layout (8KB per chunk).
__device__ __nv_bfloat16 g_whi[3][D_ * H_];
__device__ __nv_bfloat16 g_wlo[3][D_ * H_];

// ===========================================================================
// helpers
// ===========================================================================
__device__ __forceinline__ uint32_t smem_u32(const void* p) {
    uint32_t a;
    asm("{ .reg .u64 t; cvta.to.shared.u64 t, %1; cvt.u32.u64 %0, t; }" : "=r"(a) : "l"(p));
    return a;
}
__device__ __forceinline__ uint32_t pack2(__nv_bfloat16 a, __nv_bfloat16 b) {
    return (uint32_t)__bfloat16_as_ushort(a) | ((uint32_t)__bfloat16_as_ushort(b) << 16);
}
__device__ __forceinline__ void split2(float a, float b, uint32_t& hi, uint32_t& lo) {
    __nv_bfloat16 ha = __float2bfloat16(a), hb = __float2bfloat16(b);
    hi = pack2(ha, hb);
    lo = pack2(__float2bfloat16(a - __bfloat162float(ha)),
               __float2bfloat16(b - __bfloat162float(hb)));
}

__device__ __forceinline__ void ldsm4(uint32_t& r0, uint32_t& r1, uint32_t& r2, uint32_t& r3, uint32_t addr) {
    asm volatile("ldmatrix.sync.aligned.m8n8.x4.shared.b16 {%0,%1,%2,%3}, [%4];"
        : "=r"(r0), "=r"(r1), "=r"(r2), "=r"(r3) : "r"(addr));
}
__device__ __forceinline__ void ldsm4t(uint32_t& r0, uint32_t& r1, uint32_t& r2, uint32_t& r3, uint32_t addr) {
    asm volatile("ldmatrix.sync.aligned.m8n8.x4.trans.shared.b16 {%0,%1,%2,%3}, [%4];"
        : "=r"(r0), "=r"(r1), "=r"(r2), "=r"(r3) : "r"(addr));
}
__device__ __forceinline__ void mma16816(float& d0, float& d1, float& d2, float& d3,
                                          uint32_t a0, uint32_t a1, uint32_t a2, uint32_t a3,
                                          uint32_t b0, uint32_t b1) {
    asm volatile("mma.sync.aligned.m16n8k16.row.col.f32.bf16.bf16.f32 "
        "{%0,%1,%2,%3}, {%4,%5,%6,%7}, {%8,%9}, {%0,%1,%2,%3};"
        : "+f"(d0), "+f"(d1), "+f"(d2), "+f"(d3)
        : "r"(a0), "r"(a1), "r"(a2), "r"(a3), "r"(b0), "r"(b1));
}

#define CP_ASYNC16(dst, src) \
    asm volatile("cp.async.cg.shared.global [%0], [%1], 16;" :: "r"(dst), "l"(src))
#define CP_COMMIT() asm volatile("cp.async.commit_group;" ::: "memory")
#define CP_WAIT(n)  asm volatile("cp.async.wait_group %0;" :: "n"(n) : "memory")

// ===========================================================================
// Kernel 0: pre-split W matrices into bf16 hi/lo, per-chunk swizzled tiles.
// Grid (16 chunks, 3 mats), block 256.
// ===========================================================================
__global__ __launch_bounds__(256) void split_w_kernel(
    const float* __restrict__ Wq, const float* __restrict__ Wk, const float* __restrict__ Wv)
{
    const int ck = blockIdx.x, m = blockIdx.y, tid = threadIdx.x;
    const float4* W4 = (const float4*)((m == 0) ? Wq : ((m == 1) ? Wk : Wv));
    char* hiB = (char*)g_whi[m] + ck * 8192;
    char* loB = (char*)g_wlo[m] + ck * 8192;
    #pragma unroll
    for (int j = 0; j < 4; j++) {
        int f = tid + j * 256;              // 0..1023
        int r = f >> 4, c4 = f & 15;
        float4 v = W4[(size_t)(ck * 64 + r) * 16 + c4];
        uint32_t h0, l0, h1, l1;
        split2(v.x, v.y, h0, l0);
        split2(v.z, v.w, h1, l1);
        uint32_t so = (uint32_t)(r * 128 + (((c4 >> 1) ^ (r & 7)) << 4) + (c4 & 1) * 8);
        *(uint32_t*)(hiB + so)     = h0;
        *(uint32_t*)(hiB + so + 4) = h1;
        *(uint32_t*)(loB + so)     = l0;
        *(uint32_t*)(loB + so + 4) = l1;
    }
}

// ===========================================================================
// Kernel 1: fused QKV projection + LayerNorm via mma.sync bf16x3.
// W tiles arrive via cp.async from pre-split buffers; X converted in-flight.
// ===========================================================================
#define P_XHI 0
#define P_XLO 16384
#define P_W0H 32768
#define P_WSTRIDE 8192
#define PROJ_SMEM (32768 + 6 * 8192)

__global__ __launch_bounds__(256) void proj_ln_kernel(const float* __restrict__ X)
{
    extern __shared__ char smem[];
    const uint32_t sb = smem_u32(smem);
    const int tid  = threadIdx.x;
    const int warp = tid >> 5, lane = tid & 31;
    const int wrow = warp * 16;
    const int mt   = blockIdx.x;

    float a0[3][8], a1[3][8], a2[3][8], a3[3][8];
    #pragma unroll
    for (int m = 0; m < 3; m++)
        #pragma unroll
        for (int nc = 0; nc < 8; nc++) { a0[m][nc]=0.f; a1[m][nc]=0.f; a2[m][nc]=0.f; a3[m][nc]=0.f; }

    const float4* X4 = (const float4*)X;

    const int arow = wrow + (lane & 15);
    const int as7  = arow & 7;
    const int abit = lane >> 4;
    const int krv  = lane & 15;
    const int vbit = lane >> 4;
    const int s7   = lane & 7;

    for (int kk = 0; kk < D_; kk += 64) {
        __syncthreads();   // previous iter's ldsm done

        // ---- W tiles via cp.async (pre-split, already swizzled) ----
        #pragma unroll
        for (int m = 0; m < 3; m++) {
            const char* srcH = (const char*)g_whi[m] + (kk >> 6) * 8192;
            const char* srcL = (const char*)g_wlo[m] + (kk >> 6) * 8192;
            #pragma unroll
            for (int j = 0; j < 2; j++) {
                int f16 = (tid + j * 256) * 16;     // 0..8191 step 16
                CP_ASYNC16(sb + P_W0H + (uint32_t)(m * 2 * P_WSTRIDE) + f16, srcH + f16);
                CP_ASYNC16(sb + P_W0H + (uint32_t)((m * 2 + 1) * P_WSTRIDE) + f16, srcL + f16);
            }
        }
        CP_COMMIT();

        // ---- stage X chunk [128 rows][64 k] -> bf16 hi/lo, swizzled ----
        #pragma unroll
        for (int j = 0; j < 8; j++) {
            int f = tid + j * 256;
            int r = f >> 4, c4 = f & 15;
            float4 v = X4[(size_t)(mt * 128 + r) * 256 + (kk >> 2) + c4];
            uint32_t h0, l0, h1, l1;
            split2(v.x, v.y, h0, l0);
            split2(v.z, v.w, h1, l1);
            uint32_t so = (uint32_t)(r * 128 + (((c4 >> 1) ^ (r & 7)) << 4) + (c4 & 1) * 8);
            *(uint32_t*)(smem + P_XHI + so)     = h0;
            *(uint32_t*)(smem + P_XHI + so + 4) = h1;
            *(uint32_t*)(smem + P_XLO + so)     = l0;
            *(uint32_t*)(smem + P_XLO + so + 4) = l1;
        }
        CP_WAIT(0);
        __syncthreads();

        // ---- A fragments (X rows) ----
        uint32_t xh[4][4], xl[4][4];
        #pragma unroll
        for (int kc = 0; kc < 4; kc++) {
            int c16 = 2 * kc + abit;
            uint32_t ad = sb + P_XHI + (uint32_t)(arow * 128) + ((c16 ^ as7) << 4);
            ldsm4(xh[kc][0], xh[kc][1], xh[kc][2], xh[kc][3], ad);
            ldsm4(xl[kc][0], xl[kc][1], xl[kc][2], xl[kc][3], ad + (P_XLO - P_XHI));
        }

        // ---- 3 GEMMs, bf16x3 ----
        #pragma unroll
        for (int m = 0; m < 3; m++) {
            uint32_t wbase = sb + P_W0H + (uint32_t)(m * 2 * P_WSTRIDE);
            #pragma unroll
            for (int kc = 0; kc < 4; kc++) {
                #pragma unroll
                for (int ncp = 0; ncp < 4; ncp++) {
                    uint32_t ad = wbase + (uint32_t)((kc * 16 + krv) * 128)
                                + (((2 * ncp + vbit) ^ s7) << 4);
                    uint32_t bh0, bh1, bh2, bh3, bl0, bl1, bl2, bl3;
                    ldsm4t(bh0, bh1, bh2, bh3, ad);
                    ldsm4t(bl0, bl1, bl2, bl3, ad + P_WSTRIDE);
                    int n = 2 * ncp;
                    mma16816(a0[m][n], a1[m][n], a2[m][n], a3[m][n],
                             xh[kc][0], xh[kc][1], xh[kc][2], xh[kc][3], bh0, bh1);
                    mma16816(a0[m][n], a1[m][n], a2[m][n], a3[m][n],
                             xl[kc][0], xl[kc][1], xl[kc][2], xl[kc][3], bh0, bh1);
                    mma16816(a0[m][n], a1[m][n], a2[m][n], a3[m][n],
                             xh[kc][0], xh[kc][1], xh[kc][2], xh[kc][3], bl0, bl1);
                    mma16816(a0[m][n+1], a1[m][n+1], a2[m][n+1], a3[m][n+1],
                             xh[kc][0], xh[kc][1], xh[kc][2], xh[kc][3], bh2, bh3);
                    mma16816(a0[m][n+1], a1[m][n+1], a2[m][n+1], a3[m][n+1],
                             xl[kc][0], xl[kc][1], xl[kc][2], xl[kc][3], bh2, bh3);
                    mma16816(a0[m][n+1], a1[m][n+1], a2[m][n+1], a3[m][n+1],
                             xh[kc][0], xh[kc][1], xh[kc][2], xh[kc][3], bl2, bl3);
                }
            }
        }
    }

    // ---- epilogue: LayerNorm (Q,K) in registers + quad shuffles, split + store ----
    const int rA = mt * 128 + wrow + (lane >> 2);
    const int rB = rA + 8;

    #pragma unroll
    for (int m = 0; m < 3; m++) {
        float mu0 = 0.f, mu1 = 0.f, rs0 = 1.f, rs1 = 1.f;
        if (m < 2) {
            float sum0 = 0.f, sum1 = 0.f;
            #pragma unroll
            for (int nc = 0; nc < 8; nc++) {
                sum0 += a0[m][nc] + a1[m][nc];
                sum1 += a2[m][nc] + a3[m][nc];
            }
            sum0 += __shfl_xor_sync(0xffffffffu, sum0, 1);
            sum0 += __shfl_xor_sync(0xffffffffu, sum0, 2);
            sum1 += __shfl_xor_sync(0xffffffffu, sum1, 1);
            sum1 += __shfl_xor_sync(0xffffffffu, sum1, 2);
            mu0 = sum0 * (1.0f / 64.0f);
            mu1 = sum1 * (1.0f / 64.0f);
            float v0 = 0.f, v1 = 0.f;
            #pragma unroll
            for (int nc = 0; nc < 8; nc++) {
                float d00 = a0[m][nc] - mu0, d01 = a1[m][nc] - mu0;
                float d10 = a2[m][nc] - mu1, d11 = a3[m][nc] - mu1;
                v0 += d00 * d00 + d01 * d01;
                v1 += d10 * d10 + d11 * d11;
            }
            v0 += __shfl_xor_sync(0xffffffffu, v0, 1);
            v0 += __shfl_xor_sync(0xffffffffu, v0, 2);
            v1 += __shfl_xor_sync(0xffffffffu, v1, 1);
            v1 += __shfl_xor_sync(0xffffffffu, v1, 2);
            rs0 = rsqrtf(v0 * (1.0f / 64.0f) + 1e-5f);
            rs1 = rsqrtf(v1 * (1.0f / 64.0f) + 1e-5f);
        }
        const float sc = (m == 0) ? 0.125f : 1.0f;
        rs0 *= sc; rs1 *= sc;

        uint32_t* ghi32 = (uint32_t*)((m == 0) ? g_qhi : ((m == 1) ? g_khi : g_vhi));
        uint32_t* glo32 = (uint32_t*)((m == 0) ? g_qlo : ((m == 1) ? g_klo : g_vlo));

        #pragma unroll
        for (int nc = 0; nc < 8; nc++) {
            uint32_t hA, lA, hB, lB;
            split2((a0[m][nc] - mu0) * rs0, (a1[m][nc] - mu0) * rs0, hA, lA);
            split2((a2[m][nc] - mu1) * rs1, (a3[m][nc] - mu1) * rs1, hB, lB);
            size_t iA = (size_t)rA * 32 + nc * 4 + (lane & 3);
            size_t iB = (size_t)rB * 32 + nc * 4 + (lane & 3);
            ghi32[iA] = hA; glo32[iA] = lA;
            ghi32[iB] = hB; glo32[iB] = lB;
        }
    }
}

// ===========================================================================
// Kernel 2: flash attention, mma.sync bf16x3, cp.async double-buffered K/V.
// SMEM: 2 buffers x 64KB (KHI/KLO/VHI/VLO 16KB each) = 128KB.
// ===========================================================================
#define OFF_KHI 0
#define OFF_KLO 16384
#define OFF_VHI 32768
#define OFF_VLO 49152
#define TB      65536
#define NT      (S_ / 128)
#define ATTN_SMEM (2 * TB)

__global__ __launch_bounds__(256) void attn_mma_kernel(float* __restrict__ out)
{
    extern __shared__ char smem[];
    const uint32_t sb = smem_u32(smem);
    const int tid  = threadIdx.x;
    const int warp = tid >> 5, lane = tid & 31;
    const int wrow = warp * 16;

    const int qbase = blockIdx.x * 128;
    const int b     = qbase / S_;

    // ---- stage Q into buf0, grab A fragments ----
    {
        const uint4* qh4 = (const uint4*)((const char*)g_qhi + (size_t)qbase * 128);
        const uint4* ql4 = (const uint4*)((const char*)g_qlo + (size_t)qbase * 128);
        #pragma unroll
        for (int j = 0; j < 4; j++) {
            int f = tid + j * 256;
            int r = f >> 3, c = f & 7;
            uint32_t so = r * 128 + ((c ^ (r & 7)) << 4);
            *(uint4*)(smem + OFF_KHI + so) = qh4[f];
            *(uint4*)(smem + OFF_KLO + so) = ql4[f];
        }
    }
    __syncthreads();

    uint32_t qh[4][4], ql[4][4];
    {
        int arow = wrow + (lane & 15);
        int as7  = arow & 7;
        #pragma unroll
        for (int kc = 0; kc < 4; kc++) {
            int c16 = 2 * kc + (lane >> 4);
            uint32_t ad = sb + OFF_KHI + arow * 128 + ((c16 ^ as7) << 4);
            ldsm4(qh[kc][0], qh[kc][1], qh[kc][2], qh[kc][3], ad);
            ldsm4(ql[kc][0], ql[kc][1], ql[kc][2], ql[kc][3], ad + (OFF_KLO - OFF_KHI));
        }
    }
    __syncthreads();   // all warps have Q fragments; buf0 free for tile 0

    const char* khB = (const char*)g_khi + (size_t)(b * S_) * 128;
    const char* klB = (const char*)g_klo + (size_t)(b * S_) * 128;
    const char* vhB = (const char*)g_vhi + (size_t)(b * S_) * 128;
    const char* vlB = (const char*)g_vlo + (size_t)(b * S_) * 128;

    // prefetch tile 0 -> buf 0
    {
        uint32_t dst = sb;
        #pragma unroll
        for (int j = 0; j < 4; j++) {
            int f = tid + j * 256;
            int r = f >> 3, c = f & 7;
            uint32_t so = r * 128 + ((c ^ (r & 7)) << 4);
            int gs = f * 16;
            CP_ASYNC16(dst + OFF_KHI + so, khB + gs);
            CP_ASYNC16(dst + OFF_KLO + so, klB + gs);
            CP_ASYNC16(dst + OFF_VHI + so, vhB + gs);
            CP_ASYNC16(dst + OFF_VLO + so, vlB + gs);
        }
        CP_COMMIT();
    }

    float s0[16], s1[16], s2[16], s3[16];
    float o0[8], o1[8], o2[8], o3[8];
    #pragma unroll
    for (int i = 0; i < 8; i++) { o0[i] = 0.f; o1[i] = 0.f; o2[i] = 0.f; o3[i] = 0.f; }
    float m0 = -INFINITY, m1 = -INFINITY, l0 = 0.f, l1 = 0.f;

    const int s7   = lane & 7;
    const int krq  = (lane & 7) + ((lane >> 4) << 3);
    const int cbit = (lane >> 3) & 1;
    const int krv  = lane & 15;
    const int vbit = lane >> 4;

    for (int kt = 0; kt < NT; kt++) {
        __syncthreads();   // everyone finished reading the buffer we're about to overwrite

        // prefetch tile kt+1 into the other buffer
        if (kt + 1 < NT) {
            uint32_t dst = sb + ((kt + 1) & 1) * TB;
            size_t gb = (size_t)((kt + 1) * 128) * 128;
            #pragma unroll
            for (int j = 0; j < 4; j++) {
                int f = tid + j * 256;
                int r = f >> 3, c = f & 7;
                uint32_t so = r * 128 + ((c ^ (r & 7)) << 4);
                size_t gs = gb + f * 16;
                CP_ASYNC16(dst + OFF_KHI + so, khB + gs);
                CP_ASYNC16(dst + OFF_KLO + so, klB + gs);
                CP_ASYNC16(dst + OFF_VHI + so, vhB + gs);
                CP_ASYNC16(dst + OFF_VLO + so, vlB + gs);
            }
            CP_COMMIT();
            CP_WAIT(1);
        } else {
            CP_WAIT(0);
        }
        __syncthreads();

        const uint32_t bufb = sb + (kt & 1) * TB;

        // ---- S = Q K^T (bf16x3) ----
        #pragma unroll
        for (int i = 0; i < 16; i++) { s0[i] = 0.f; s1[i] = 0.f; s2[i] = 0.f; s3[i] = 0.f; }
        #pragma unroll
        for (int kc = 0; kc < 4; kc++) {
            #pragma unroll
            for (int ncp = 0; ncp < 8; ncp++) {
                uint32_t ad = bufb + OFF_KHI + (uint32_t)(ncp * 16 + krq) * 128
                            + (((2 * kc + cbit) ^ s7) << 4);
                uint32_t bh0, bh1, bh2, bh3, bl0, bl1, bl2, bl3;
                ldsm4(bh0, bh1, bh2, bh3, ad);
                ldsm4(bl0, bl1, bl2, bl3, ad + (OFF_KLO - OFF_KHI));
                int n = 2 * ncp;
                mma16816(s0[n], s1[n], s2[n], s3[n], qh[kc][0], qh[kc][1], qh[kc][2], qh[kc][3], bh0, bh1);
                mma16816(s0[n], s1[n], s2[n], s3[n], ql[kc][0], ql[kc][1], ql[kc][2], ql[kc][3], bh0, bh1);
                mma16816(s0[n], s1[n], s2[n], s3[n], qh[kc][0], qh[kc][1], qh[kc][2], qh[kc][3], bl0, bl1);
                mma16816(s0[n+1], s1[n+1], s2[n+1], s3[n+1], qh[kc][0], qh[kc][1], qh[kc][2], qh[kc][3], bh2, bh3);
                mma16816(s0[n+1], s1[n+1], s2[n+1], s3[n+1], ql[kc][0], ql[kc][1], ql[kc][2], ql[kc][3], bh2, bh3);
                mma16816(s0[n+1], s1[n+1], s2[n+1], s3[n+1], qh[kc][0], qh[kc][1], qh[kc][2], qh[kc][3], bl2, bl3);
            }
        }

        // ---- online softmax ----
        float tmax0 = -INFINITY, tmax1 = -INFINITY;
        #pragma unroll
        for (int i = 0; i < 16; i++) {
            tmax0 = fmaxf(tmax0, fmaxf(s0[i], s1[i]));
            tmax1 = fmaxf(tmax1, fmaxf(s2[i], s3[i]));
        }
        tmax0 = fmaxf(tmax0, __shfl_xor_sync(0xffffffffu, tmax0, 1));
        tmax0 = fmaxf(tmax0, __shfl_xor_sync(0xffffffffu, tmax0, 2));
        tmax1 = fmaxf(tmax1, __shfl_xor_sync(0xffffffffu, tmax1, 1));
        tmax1 = fmaxf(tmax1, __shfl_xor_sync(0xffffffffu, tmax1, 2));

        float mn0 = fmaxf(m0, tmax0), mn1 = fmaxf(m1, tmax1);
        float corr0 = __expf(m0 - mn0), corr1 = __expf(m1 - mn1);

        float sum0 = 0.f, sum1 = 0.f;
        #pragma unroll
        for (int i = 0; i < 16; i++) {
            s0[i] = __expf(s0[i] - mn0); s1[i] = __expf(s1[i] - mn0);
            s2[i] = __expf(s2[i] - mn1); s3[i] = __expf(s3[i] - mn1);
            sum0 += s0[i] + s1[i];
            sum1 += s2[i] + s3[i];
        }
        sum0 += __shfl_xor_sync(0xffffffffu, sum0, 1);
        sum0 += __shfl_xor_sync(0xffffffffu, sum0, 2);
        sum1 += __shfl_xor_sync(0xffffffffu, sum1, 1);
        sum1 += __shfl_xor_sync(0xffffffffu, sum1, 2);

        l0 = l0 * corr0 + sum0;  m0 = mn0;
        l1 = l1 * corr1 + sum1;  m1 = mn1;
        #pragma unroll
        for (int i = 0; i < 8; i++) {
            o0[i] *= corr0; o1[i] *= corr0;
            o2[i] *= corr1; o3[i] *= corr1;
        }

        // ---- O += P V (bf16x3) ----
        #pragma unroll
        for (int kc = 0; kc < 8; kc++) {
            uint32_t ph0, ph1, ph2, ph3, pl0, pl1, pl2, pl3;
            split2(s0[2*kc],   s1[2*kc],   ph0, pl0);
            split2(s2[2*kc],   s3[2*kc],   ph1, pl1);
            split2(s0[2*kc+1], s1[2*kc+1], ph2, pl2);
            split2(s2[2*kc+1], s3[2*kc+1], ph3, pl3);
            #pragma unroll
            for (int ncp = 0; ncp < 4; ncp++) {
                uint32_t ad = bufb + OFF_VHI + (uint32_t)(kc * 16 + krv) * 128
                            + (((2 * ncp + vbit) ^ s7) << 4);
                uint32_t bh0, bh1, bh2, bh3, bl0, bl1, bl2, bl3;
                ldsm4t(bh0, bh1, bh2, bh3, ad);
                ldsm4t(bl0, bl1, bl2, bl3, ad + (OFF_VLO - OFF_VHI));
                int n = 2 * ncp;
                mma16816(o0[n], o1[n], o2[n], o3[n], ph0, ph1, ph2, ph3, bh0, bh1);
                mma16816(o0[n], o1[n], o2[n], o3[n], pl0, pl1, pl2, pl3, bh0, bh1);
                mma16816(o0[n], o1[n], o2[n], o3[n], ph0, ph1, ph2, ph3, bl0, bl1);
                mma16816(o0[n+1], o1[n+1], o2[n+1], o3[n+1], ph0, ph1, ph2, ph3, bh2, bh3);
                mma16816(o0[n+1], o1[n+1], o2[n+1], o3[n+1], pl0, pl1, pl2, pl3, bh2, bh3);
                mma16816(o0[n+1], o1[n+1], o2[n+1], o3[n+1], ph0, ph1, ph2, ph3, bl2, bl3);
            }
        }
    }

    const float il0 = 1.0f / l0, il1 = 1.0f / l1;
    const int r  = lane >> 2;
    const int c2 = (lane & 3) * 2;
    float2* out2 = (float2*)out;
    #pragma unroll
    for (int nc = 0; nc < 8; nc++) {
        size_t i_lo = ((size_t)(qbase + wrow + r)     * 64 + 8 * nc + c2) >> 1;
        size_t i_hi = ((size_t)(qbase + wrow + r + 8) * 64 + 8 * nc + c2) >> 1;
        out2[i_lo] = make_float2(o0[nc] * il0, o1[nc] * il0);
        out2[i_hi] = make_float2(o2[nc] * il1, o3[nc] * il1);
    }
}

// ===========================================================================
// Launch
// ===========================================================================
extern "C" void kernel_launch(void* const* d_in, const int* in_sizes, int n_in,
                              void* d_out, int out_size)
{
    const float* X  = (const float*)d_in[0];
    const float* Wq = (const float*)d_in[1];
    const float* Wk = (const float*)d_in[2];
    const float* Wv = (const float*)d_in[3];
    float* out = (float*)d_out;

    dim3 gw(16, 3);
    split_w_kernel<<<gw, 256>>>(Wq, Wk, Wv);

    cudaFuncSetAttribute(proj_ln_kernel, cudaFuncAttributeMaxDynamicSharedMemorySize, PROJ_SMEM);
    proj_ln_kernel<<<NROWS / 128, 256, PROJ_SMEM>>>(X);

    cudaFuncSetAttribute(attn_mma_kernel, cudaFuncAttributeMaxDynamicSharedMemorySize, ATTN_SMEM);
    attn_mma_kernel<<<NROWS / 128, 256, ATTN_SMEM>>>(out);
}

// round 7
// speedup vs baseline: 6.0869x; 1.2828x over previous
#include <cuda_runtime.h>
#include <cuda_bf16.h>
#include <cuda_fp16.h>
#include <math.h>
#include <stdint.h>

// Problem shape: B=4, S=4096, D=1024, H=64
#define B_ 4
#define S_ 4096
#define D_ 1024
#define H_ 64
#define NROWS (B_ * S_)   // 16384

// Attention operands: fp16. Q stored UNSCALED as hi/lo split; K,V single fp16.
__device__ __half g_qhi[NROWS * H_];
__device__ __half g_qlo[NROWS * H_];
__device__ __half g_khi[NROWS * H_];
__device__ __half g_vhi[NROWS * H_];
// Pre-split W (bf16 hi/lo) in per-64k-chunk swizzled tile layout (8KB per chunk).
__device__ __nv_bfloat16 g_whi[3][D_ * H_];
__device__ __nv_bfloat16 g_wlo[3][D_ * H_];

// ===========================================================================
// helpers
// ===========================================================================
__device__ __forceinline__ uint32_t smem_u32(const void* p) {
    uint32_t a;
    asm("{ .reg .u64 t; cvta.to.shared.u64 t, %1; cvt.u32.u64 %0, t; }" : "=r"(a) : "l"(p));
    return a;
}
__device__ __forceinline__ uint32_t pack2(__nv_bfloat16 a, __nv_bfloat16 b) {
    return (uint32_t)__bfloat16_as_ushort(a) | ((uint32_t)__bfloat16_as_ushort(b) << 16);
}
__device__ __forceinline__ void split2(float a, float b, uint32_t& hi, uint32_t& lo) {
    __nv_bfloat16 ha = __float2bfloat16(a), hb = __float2bfloat16(b);
    hi = pack2(ha, hb);
    lo = pack2(__float2bfloat16(a - __bfloat162float(ha)),
               __float2bfloat16(b - __bfloat162float(hb)));
}
// fp16 pack / split
__device__ __forceinline__ uint32_t pack2h(__half a, __half b) {
    return (uint32_t)__half_as_ushort(a) | ((uint32_t)__half_as_ushort(b) << 16);
}
__device__ __forceinline__ uint32_t packh(float a, float b) {
    return pack2h(__float2half_rn(a), __float2half_rn(b));
}
__device__ __forceinline__ void split2h(float a, float b, uint32_t& hi, uint32_t& lo) {
    __half ha = __float2half_rn(a), hb = __float2half_rn(b);
    hi = pack2h(ha, hb);
    lo = pack2h(__float2half_rn(a - __half2float(ha)),
                __float2half_rn(b - __half2float(hb)));
}

__device__ __forceinline__ void ldsm4(uint32_t& r0, uint32_t& r1, uint32_t& r2, uint32_t& r3, uint32_t addr) {
    asm volatile("ldmatrix.sync.aligned.m8n8.x4.shared.b16 {%0,%1,%2,%3}, [%4];"
        : "=r"(r0), "=r"(r1), "=r"(r2), "=r"(r3) : "r"(addr));
}
__device__ __forceinline__ void ldsm4t(uint32_t& r0, uint32_t& r1, uint32_t& r2, uint32_t& r3, uint32_t addr) {
    asm volatile("ldmatrix.sync.aligned.m8n8.x4.trans.shared.b16 {%0,%1,%2,%3}, [%4];"
        : "=r"(r0), "=r"(r1), "=r"(r2), "=r"(r3) : "r"(addr));
}
// bf16 mma (projection)
__device__ __forceinline__ void mma16816(float& d0, float& d1, float& d2, float& d3,
                                          uint32_t a0, uint32_t a1, uint32_t a2, uint32_t a3,
                                          uint32_t b0, uint32_t b1) {
    asm volatile("mma.sync.aligned.m16n8k16.row.col.f32.bf16.bf16.f32 "
        "{%0,%1,%2,%3}, {%4,%5,%6,%7}, {%8,%9}, {%0,%1,%2,%3};"
        : "+f"(d0), "+f"(d1), "+f"(d2), "+f"(d3)
        : "r"(a0), "r"(a1), "r"(a2), "r"(a3), "r"(b0), "r"(b1));
}
// fp16 mma (attention)
__device__ __forceinline__ void mma16816h(float& d0, float& d1, float& d2, float& d3,
                                           uint32_t a0, uint32_t a1, uint32_t a2, uint32_t a3,
                                           uint32_t b0, uint32_t b1) {
    asm volatile("mma.sync.aligned.m16n8k16.row.col.f32.f16.f16.f32 "
        "{%0,%1,%2,%3}, {%4,%5,%6,%7}, {%8,%9}, {%0,%1,%2,%3};"
        : "+f"(d0), "+f"(d1), "+f"(d2), "+f"(d3)
        : "r"(a0), "r"(a1), "r"(a2), "r"(a3), "r"(b0), "r"(b1));
}

#define CP_ASYNC16(dst, src) \
    asm volatile("cp.async.cg.shared.global [%0], [%1], 16;" :: "r"(dst), "l"(src))
#define CP_COMMIT() asm volatile("cp.async.commit_group;" ::: "memory")
#define CP_WAIT(n)  asm volatile("cp.async.wait_group %0;" :: "n"(n) : "memory")

// ===========================================================================
// Kernel 0: pre-split W matrices into bf16 hi/lo, per-chunk swizzled tiles.
// ===========================================================================
__global__ __launch_bounds__(256) void split_w_kernel(
    const float* __restrict__ Wq, const float* __restrict__ Wk, const float* __restrict__ Wv)
{
    const int ck = blockIdx.x, m = blockIdx.y, tid = threadIdx.x;
    const float4* W4 = (const float4*)((m == 0) ? Wq : ((m == 1) ? Wk : Wv));
    char* hiB = (char*)g_whi[m] + ck * 8192;
    char* loB = (char*)g_wlo[m] + ck * 8192;
    #pragma unroll
    for (int j = 0; j < 4; j++) {
        int f = tid + j * 256;
        int r = f >> 4, c4 = f & 15;
        float4 v = W4[(size_t)(ck * 64 + r) * 16 + c4];
        uint32_t h0, l0, h1, l1;
        split2(v.x, v.y, h0, l0);
        split2(v.z, v.w, h1, l1);
        uint32_t so = (uint32_t)(r * 128 + (((c4 >> 1) ^ (r & 7)) << 4) + (c4 & 1) * 8);
        *(uint32_t*)(hiB + so)     = h0;
        *(uint32_t*)(hiB + so + 4) = h1;
        *(uint32_t*)(loB + so)     = l0;
        *(uint32_t*)(loB + so + 4) = l1;
    }
}

// ===========================================================================
// Kernel 1: fused QKV projection + LayerNorm via mma.sync bf16x3.
// Epilogue stores fp16 operands for attention (Q hi/lo unscaled, K, V).
// ===========================================================================
#define P_XHI 0
#define P_XLO 16384
#define P_W0H 32768
#define P_WSTRIDE 8192
#define PROJ_SMEM (32768 + 6 * 8192)

__global__ __launch_bounds__(256) void proj_ln_kernel(const float* __restrict__ X)
{
    extern __shared__ char smem[];
    const uint32_t sb = smem_u32(smem);
    const int tid  = threadIdx.x;
    const int warp = tid >> 5, lane = tid & 31;
    const int wrow = warp * 16;
    const int mt   = blockIdx.x;

    float a0[3][8], a1[3][8], a2[3][8], a3[3][8];
    #pragma unroll
    for (int m = 0; m < 3; m++)
        #pragma unroll
        for (int nc = 0; nc < 8; nc++) { a0[m][nc]=0.f; a1[m][nc]=0.f; a2[m][nc]=0.f; a3[m][nc]=0.f; }

    const float4* X4 = (const float4*)X;

    const int arow = wrow + (lane & 15);
    const int as7  = arow & 7;
    const int abit = lane >> 4;
    const int krv  = lane & 15;
    const int vbit = lane >> 4;
    const int s7   = lane & 7;

    for (int kk = 0; kk < D_; kk += 64) {
        __syncthreads();

        #pragma unroll
        for (int m = 0; m < 3; m++) {
            const char* srcH = (const char*)g_whi[m] + (kk >> 6) * 8192;
            const char* srcL = (const char*)g_wlo[m] + (kk >> 6) * 8192;
            #pragma unroll
            for (int j = 0; j < 2; j++) {
                int f16 = (tid + j * 256) * 16;
                CP_ASYNC16(sb + P_W0H + (uint32_t)(m * 2 * P_WSTRIDE) + f16, srcH + f16);
                CP_ASYNC16(sb + P_W0H + (uint32_t)((m * 2 + 1) * P_WSTRIDE) + f16, srcL + f16);
            }
        }
        CP_COMMIT();

        #pragma unroll
        for (int j = 0; j < 8; j++) {
            int f = tid + j * 256;
            int r = f >> 4, c4 = f & 15;
            float4 v = X4[(size_t)(mt * 128 + r) * 256 + (kk >> 2) + c4];
            uint32_t h0, l0, h1, l1;
            split2(v.x, v.y, h0, l0);
            split2(v.z, v.w, h1, l1);
            uint32_t so = (uint32_t)(r * 128 + (((c4 >> 1) ^ (r & 7)) << 4) + (c4 & 1) * 8);
            *(uint32_t*)(smem + P_XHI + so)     = h0;
            *(uint32_t*)(smem + P_XHI + so + 4) = h1;
            *(uint32_t*)(smem + P_XLO + so)     = l0;
            *(uint32_t*)(smem + P_XLO + so + 4) = l1;
        }
        CP_WAIT(0);
        __syncthreads();

        uint32_t xh[4][4], xl[4][4];
        #pragma unroll
        for (int kc = 0; kc < 4; kc++) {
            int c16 = 2 * kc + abit;
            uint32_t ad = sb + P_XHI + (uint32_t)(arow * 128) + ((c16 ^ as7) << 4);
            ldsm4(xh[kc][0], xh[kc][1], xh[kc][2], xh[kc][3], ad);
            ldsm4(xl[kc][0], xl[kc][1], xl[kc][2], xl[kc][3], ad + (P_XLO - P_XHI));
        }

        #pragma unroll
        for (int m = 0; m < 3; m++) {
            uint32_t wbase = sb + P_W0H + (uint32_t)(m * 2 * P_WSTRIDE);
            #pragma unroll
            for (int kc = 0; kc < 4; kc++) {
                #pragma unroll
                for (int ncp = 0; ncp < 4; ncp++) {
                    uint32_t ad = wbase + (uint32_t)((kc * 16 + krv) * 128)
                                + (((2 * ncp + vbit) ^ s7) << 4);
                    uint32_t bh0, bh1, bh2, bh3, bl0, bl1, bl2, bl3;
                    ldsm4t(bh0, bh1, bh2, bh3, ad);
                    ldsm4t(bl0, bl1, bl2, bl3, ad + P_WSTRIDE);
                    int n = 2 * ncp;
                    mma16816(a0[m][n], a1[m][n], a2[m][n], a3[m][n],
                             xh[kc][0], xh[kc][1], xh[kc][2], xh[kc][3], bh0, bh1);
                    mma16816(a0[m][n], a1[m][n], a2[m][n], a3[m][n],
                             xl[kc][0], xl[kc][1], xl[kc][2], xl[kc][3], bh0, bh1);
                    mma16816(a0[m][n], a1[m][n], a2[m][n], a3[m][n],
                             xh[kc][0], xh[kc][1], xh[kc][2], xh[kc][3], bl0, bl1);
                    mma16816(a0[m][n+1], a1[m][n+1], a2[m][n+1], a3[m][n+1],
                             xh[kc][0], xh[kc][1], xh[kc][2], xh[kc][3], bh2, bh3);
                    mma16816(a0[m][n+1], a1[m][n+1], a2[m][n+1], a3[m][n+1],
                             xl[kc][0], xl[kc][1], xl[kc][2], xl[kc][3], bh2, bh3);
                    mma16816(a0[m][n+1], a1[m][n+1], a2[m][n+1], a3[m][n+1],
                             xh[kc][0], xh[kc][1], xh[kc][2], xh[kc][3], bl2, bl3);
                }
            }
        }
    }

    // ---- epilogue: LayerNorm (Q,K); store fp16 (Q hi/lo, K, V) ----
    const int rA = mt * 128 + wrow + (lane >> 2);
    const int rB = rA + 8;

    #pragma unroll
    for (int m = 0; m < 3; m++) {
        float mu0 = 0.f, mu1 = 0.f, rs0 = 1.f, rs1 = 1.f;
        if (m < 2) {
            float sum0 = 0.f, sum1 = 0.f;
            #pragma unroll
            for (int nc = 0; nc < 8; nc++) {
                sum0 += a0[m][nc] + a1[m][nc];
                sum1 += a2[m][nc] + a3[m][nc];
            }
            sum0 += __shfl_xor_sync(0xffffffffu, sum0, 1);
            sum0 += __shfl_xor_sync(0xffffffffu, sum0, 2);
            sum1 += __shfl_xor_sync(0xffffffffu, sum1, 1);
            sum1 += __shfl_xor_sync(0xffffffffu, sum1, 2);
            mu0 = sum0 * (1.0f / 64.0f);
            mu1 = sum1 * (1.0f / 64.0f);
            float v0 = 0.f, v1 = 0.f;
            #pragma unroll
            for (int nc = 0; nc < 8; nc++) {
                float d00 = a0[m][nc] - mu0, d01 = a1[m][nc] - mu0;
                float d10 = a2[m][nc] - mu1, d11 = a3[m][nc] - mu1;
                v0 += d00 * d00 + d01 * d01;
                v1 += d10 * d10 + d11 * d11;
            }
            v0 += __shfl_xor_sync(0xffffffffu, v0, 1);
            v0 += __shfl_xor_sync(0xffffffffu, v0, 2);
            v1 += __shfl_xor_sync(0xffffffffu, v1, 1);
            v1 += __shfl_xor_sync(0xffffffffu, v1, 2);
            rs0 = rsqrtf(v0 * (1.0f / 64.0f) + 1e-5f);
            rs1 = rsqrtf(v1 * (1.0f / 64.0f) + 1e-5f);
        }

        uint32_t* ghi32 = (uint32_t*)((m == 0) ? g_qhi : ((m == 1) ? g_khi : g_vhi));

        if (m == 0) {
            // Q: fp16 hi/lo split, UNSCALED (0.125 folded into attn softmax)
            uint32_t* glo32 = (uint32_t*)g_qlo;
            #pragma unroll
            for (int nc = 0; nc < 8; nc++) {
                uint32_t hA, lA, hB, lB;
                split2h((a0[m][nc] - mu0) * rs0, (a1[m][nc] - mu0) * rs0, hA, lA);
                split2h((a2[m][nc] - mu1) * rs1, (a3[m][nc] - mu1) * rs1, hB, lB);
                size_t iA = (size_t)rA * 32 + nc * 4 + (lane & 3);
                size_t iB = (size_t)rB * 32 + nc * 4 + (lane & 3);
                ghi32[iA] = hA; glo32[iA] = lA;
                ghi32[iB] = hB; glo32[iB] = lB;
            }
        } else {
            #pragma unroll
            for (int nc = 0; nc < 8; nc++) {
                uint32_t hA = packh((a0[m][nc] - mu0) * rs0, (a1[m][nc] - mu0) * rs0);
                uint32_t hB = packh((a2[m][nc] - mu1) * rs1, (a3[m][nc] - mu1) * rs1);
                size_t iA = (size_t)rA * 32 + nc * 4 + (lane & 3);
                size_t iB = (size_t)rB * 32 + nc * 4 + (lane & 3);
                ghi32[iA] = hA;
                ghi32[iB] = hB;
            }
        }
    }
}

// ===========================================================================
// Kernel 2: flash attention, fp16 mma.sync; QK 2-pass (Q hi/lo), PV 2-pass
// (P hi/lo). cp.async double-buffered K/V, 32KB/buffer.
// ===========================================================================
#define OFF_KHI 0
#define OFF_VHI 16384
#define TB      32768
#define NT      (S_ / 128)
#define ATTN_SMEM (2 * TB)

__global__ __launch_bounds__(256) void attn_mma_kernel(float* __restrict__ out)
{
    extern __shared__ char smem[];
    const uint32_t sb = smem_u32(smem);
    const int tid  = threadIdx.x;
    const int warp = tid >> 5, lane = tid & 31;
    const int wrow = warp * 16;

    const int qbase = blockIdx.x * 128;
    const int b     = qbase / S_;

    // ---- stage Q (hi->K area, lo->V area of buf0), grab A fragments ----
    {
        const uint4* qh4 = (const uint4*)((const char*)g_qhi + (size_t)qbase * 128);
        const uint4* ql4 = (const uint4*)((const char*)g_qlo + (size_t)qbase * 128);
        #pragma unroll
        for (int j = 0; j < 4; j++) {
            int f = tid + j * 256;
            int r = f >> 3, c = f & 7;
            uint32_t so = r * 128 + ((c ^ (r & 7)) << 4);
            *(uint4*)(smem + OFF_KHI + so) = qh4[f];
            *(uint4*)(smem + OFF_VHI + so) = ql4[f];
        }
    }
    __syncthreads();

    uint32_t qh[4][4], ql[4][4];
    {
        int arow = wrow + (lane & 15);
        int as7  = arow & 7;
        #pragma unroll
        for (int kc = 0; kc < 4; kc++) {
            int c16 = 2 * kc + (lane >> 4);
            uint32_t ad = sb + OFF_KHI + arow * 128 + ((c16 ^ as7) << 4);
            ldsm4(qh[kc][0], qh[kc][1], qh[kc][2], qh[kc][3], ad);
            ldsm4(ql[kc][0], ql[kc][1], ql[kc][2], ql[kc][3], ad + (OFF_VHI - OFF_KHI));
        }
    }
    __syncthreads();

    const char* khB = (const char*)g_khi + (size_t)(b * S_) * 128;
    const char* vhB = (const char*)g_vhi + (size_t)(b * S_) * 128;

    // prefetch tile 0 -> buf 0
    {
        #pragma unroll
        for (int j = 0; j < 4; j++) {
            int f = tid + j * 256;
            int r = f >> 3, c = f & 7;
            uint32_t so = r * 128 + ((c ^ (r & 7)) << 4);
            int gs = f * 16;
            CP_ASYNC16(sb + OFF_KHI + so, khB + gs);
            CP_ASYNC16(sb + OFF_VHI + so, vhB + gs);
        }
        CP_COMMIT();
    }

    float s0[16], s1[16], s2[16], s3[16];
    float o0[8], o1[8], o2[8], o3[8];
    #pragma unroll
    for (int i = 0; i < 8; i++) { o0[i] = 0.f; o1[i] = 0.f; o2[i] = 0.f; o3[i] = 0.f; }
    float m0 = -INFINITY, m1 = -INFINITY, l0 = 0.f, l1 = 0.f;

    const int s7   = lane & 7;
    const int krq  = (lane & 7) + ((lane >> 4) << 3);
    const int cbit = (lane >> 3) & 1;
    const int krv  = lane & 15;
    const int vbit = lane >> 4;
    const float scale = 0.125f;   // 1/sqrt(64), applied post-MMA

    for (int kt = 0; kt < NT; kt++) {
        __syncthreads();

        if (kt + 1 < NT) {
            uint32_t dst = sb + ((kt + 1) & 1) * TB;
            size_t gb = (size_t)((kt + 1) * 128) * 128;
            #pragma unroll
            for (int j = 0; j < 4; j++) {
                int f = tid + j * 256;
                int r = f >> 3, c = f & 7;
                uint32_t so = r * 128 + ((c ^ (r & 7)) << 4);
                size_t gs = gb + f * 16;
                CP_ASYNC16(dst + OFF_KHI + so, khB + gs);
                CP_ASYNC16(dst + OFF_VHI + so, vhB + gs);
            }
            CP_COMMIT();
            CP_WAIT(1);
        } else {
            CP_WAIT(0);
        }
        __syncthreads();

        const uint32_t bufb = sb + (kt & 1) * TB;

        // ---- S = Q K^T : (Qhi + Qlo) * K, fp16 ----
        #pragma unroll
        for (int i = 0; i < 16; i++) { s0[i] = 0.f; s1[i] = 0.f; s2[i] = 0.f; s3[i] = 0.f; }
        #pragma unroll
        for (int kc = 0; kc < 4; kc++) {
            #pragma unroll
            for (int ncp = 0; ncp < 8; ncp++) {
                uint32_t ad = bufb + OFF_KHI + (uint32_t)(ncp * 16 + krq) * 128
                            + (((2 * kc + cbit) ^ s7) << 4);
                uint32_t bh0, bh1, bh2, bh3;
                ldsm4(bh0, bh1, bh2, bh3, ad);
                int n = 2 * ncp;
                mma16816h(s0[n], s1[n], s2[n], s3[n], qh[kc][0], qh[kc][1], qh[kc][2], qh[kc][3], bh0, bh1);
                mma16816h(s0[n], s1[n], s2[n], s3[n], ql[kc][0], ql[kc][1], ql[kc][2], ql[kc][3], bh0, bh1);
                mma16816h(s0[n+1], s1[n+1], s2[n+1], s3[n+1], qh[kc][0], qh[kc][1], qh[kc][2], qh[kc][3], bh2, bh3);
                mma16816h(s0[n+1], s1[n+1], s2[n+1], s3[n+1], ql[kc][0], ql[kc][1], ql[kc][2], ql[kc][3], bh2, bh3);
            }
        }

        // ---- scale + online softmax ----
        #pragma unroll
        for (int i = 0; i < 16; i++) {
            s0[i] *= scale; s1[i] *= scale; s2[i] *= scale; s3[i] *= scale;
        }
        float tmax0 = -INFINITY, tmax1 = -INFINITY;
        #pragma unroll
        for (int i = 0; i < 16; i++) {
            tmax0 = fmaxf(tmax0, fmaxf(s0[i], s1[i]));
            tmax1 = fmaxf(tmax1, fmaxf(s2[i], s3[i]));
        }
        tmax0 = fmaxf(tmax0, __shfl_xor_sync(0xffffffffu, tmax0, 1));
        tmax0 = fmaxf(tmax0, __shfl_xor_sync(0xffffffffu, tmax0, 2));
        tmax1 = fmaxf(tmax1, __shfl_xor_sync(0xffffffffu, tmax1, 1));
        tmax1 = fmaxf(tmax1, __shfl_xor_sync(0xffffffffu, tmax1, 2));

        float mn0 = fmaxf(m0, tmax0), mn1 = fmaxf(m1, tmax1);
        float corr0 = __expf(m0 - mn0), corr1 = __expf(m1 - mn1);

        float sum0 = 0.f, sum1 = 0.f;
        #pragma unroll
        for (int i = 0; i < 16; i++) {
            s0[i] = __expf(s0[i] - mn0); s1[i] = __expf(s1[i] - mn0);
            s2[i] = __expf(s2[i] - mn1); s3[i] = __expf(s3[i] - mn1);
            sum0 += s0[i] + s1[i];
            sum1 += s2[i] + s3[i];
        }
        sum0 += __shfl_xor_sync(0xffffffffu, sum0, 1);
        sum0 += __shfl_xor_sync(0xffffffffu, sum0, 2);
        sum1 += __shfl_xor_sync(0xffffffffu, sum1, 1);
        sum1 += __shfl_xor_sync(0xffffffffu, sum1, 2);

        l0 = l0 * corr0 + sum0;  m0 = mn0;
        l1 = l1 * corr1 + sum1;  m1 = mn1;
        #pragma unroll
        for (int i = 0; i < 8; i++) {
            o0[i] *= corr0; o1[i] *= corr0;
            o2[i] *= corr1; o3[i] *= corr1;
        }

        // ---- O += P V : (Phi + Plo) * V, fp16 ----
        #pragma unroll
        for (int kc = 0; kc < 8; kc++) {
            uint32_t ph0, pl0, ph1, pl1, ph2, pl2, ph3, pl3;
            split2h(s0[2*kc],   s1[2*kc],   ph0, pl0);
            split2h(s2[2*kc],   s3[2*kc],   ph1, pl1);
            split2h(s0[2*kc+1], s1[2*kc+1], ph2, pl2);
            split2h(s2[2*kc+1], s3[2*kc+1], ph3, pl3);
            #pragma unroll
            for (int ncp = 0; ncp < 4; ncp++) {
                uint32_t ad = bufb + OFF_VHI + (uint32_t)(kc * 16 + krv) * 128
                            + (((2 * ncp + vbit) ^ s7) << 4);
                uint32_t bh0, bh1, bh2, bh3;
                ldsm4t(bh0, bh1, bh2, bh3, ad);
                int n = 2 * ncp;
                mma16816h(o0[n], o1[n], o2[n], o3[n], ph0, ph1, ph2, ph3, bh0, bh1);
                mma16816h(o0[n], o1[n], o2[n], o3[n], pl0, pl1, pl2, pl3, bh0, bh1);
                mma16816h(o0[n+1], o1[n+1], o2[n+1], o3[n+1], ph0, ph1, ph2, ph3, bh2, bh3);
                mma16816h(o0[n+1], o1[n+1], o2[n+1], o3[n+1], pl0, pl1, pl2, pl3, bh2, bh3);
            }
        }
    }

    const float il0 = 1.0f / l0, il1 = 1.0f / l1;
    const int r  = lane >> 2;
    const int c2 = (lane & 3) * 2;
    float2* out2 = (float2*)out;
    #pragma unroll
    for (int nc = 0; nc < 8; nc++) {
        size_t i_lo = ((size_t)(qbase + wrow + r)     * 64 + 8 * nc + c2) >> 1;
        size_t i_hi = ((size_t)(qbase + wrow + r + 8) * 64 + 8 * nc + c2) >> 1;
        out2[i_lo] = make_float2(o0[nc] * il0, o1[nc] * il0);
        out2[i_hi] = make_float2(o2[nc] * il1, o3[nc] * il1);
    }
}

// ===========================================================================
// Launch
// ===========================================================================
extern "C" void kernel_launch(void* const* d_in, const int* in_sizes, int n_in,
                              void* d_out, int out_size)
{
    const float* X  = (const float*)d_in[0];
    const float* Wq = (const float*)d_in[1];
    const float* Wk = (const float*)d_in[2];
    const float* Wv = (const float*)d_in[3];
    float* out = (float*)d_out;

    dim3 gw(16, 3);
    split_w_kernel<<<gw, 256>>>(Wq, Wk, Wv);

    cudaFuncSetAttribute(proj_ln_kernel, cudaFuncAttributeMaxDynamicSharedMemorySize, PROJ_SMEM);
    proj_ln_kernel<<<NROWS / 128, 256, PROJ_SMEM>>>(X);

    cudaFuncSetAttribute(attn_mma_kernel, cudaFuncAttributeMaxDynamicSharedMemorySize, ATTN_SMEM);
    attn_mma_kernel<<<NROWS / 128, 256, ATTN_SMEM>>>(out);
}

// round 8
// speedup vs baseline: 8.7577x; 1.4388x over previous
#include <cuda_runtime.h>
#include <cuda_fp16.h>
#include <math.h>
#include <stdint.h>

// Problem shape: B=4, S=4096, D=1024, H=64
#define B_ 4
#define S_ 4096
#define D_ 1024
#define H_ 64
#define NROWS (B_ * S_)   // 16384

// Attention operands (fp16). Q UNSCALED (1/sqrt(H) folded into exp2 constant).
__device__ __half g_qh[NROWS * H_];
__device__ __half g_kh[NROWS * H_];
__device__ __half g_vh[NROWS * H_];
// Pre-converted W (fp16) in per-64k-chunk swizzled tile layout (8KB per chunk).
__device__ __half g_wh[3][D_ * H_];

// ===========================================================================
// helpers
// ===========================================================================
__device__ __forceinline__ uint32_t smem_u32(const void* p) {
    uint32_t a;
    asm("{ .reg .u64 t; cvta.to.shared.u64 t, %1; cvt.u32.u64 %0, t; }" : "=r"(a) : "l"(p));
    return a;
}
// pack two floats to fp16x2 (a -> low half, b -> high half), single cvt
__device__ __forceinline__ uint32_t packhf(float a, float b) {
    uint32_t r;
    asm("cvt.rn.f16x2.f32 %0, %2, %1;" : "=r"(r) : "f"(a), "f"(b));
    return r;
}
__device__ __forceinline__ uint32_t pack2h(__half a, __half b) {
    return (uint32_t)__half_as_ushort(a) | ((uint32_t)__half_as_ushort(b) << 16);
}
// fp16 hi/lo split of two floats
__device__ __forceinline__ void split2h(float a, float b, uint32_t& hi, uint32_t& lo) {
    __half ha = __float2half_rn(a), hb = __float2half_rn(b);
    hi = pack2h(ha, hb);
    lo = packhf(a - __half2float(ha), b - __half2float(hb));
}
__device__ __forceinline__ float ex2f(float x) {
    float r;
    asm("ex2.approx.f32 %0, %1;" : "=f"(r) : "f"(x));
    return r;
}

__device__ __forceinline__ void ldsm4(uint32_t& r0, uint32_t& r1, uint32_t& r2, uint32_t& r3, uint32_t addr) {
    asm volatile("ldmatrix.sync.aligned.m8n8.x4.shared.b16 {%0,%1,%2,%3}, [%4];"
        : "=r"(r0), "=r"(r1), "=r"(r2), "=r"(r3) : "r"(addr));
}
__device__ __forceinline__ void ldsm4t(uint32_t& r0, uint32_t& r1, uint32_t& r2, uint32_t& r3, uint32_t addr) {
    asm volatile("ldmatrix.sync.aligned.m8n8.x4.trans.shared.b16 {%0,%1,%2,%3}, [%4];"
        : "=r"(r0), "=r"(r1), "=r"(r2), "=r"(r3) : "r"(addr));
}
// fp16 mma, fp32 accumulate
__device__ __forceinline__ void mma16816h(float& d0, float& d1, float& d2, float& d3,
                                           uint32_t a0, uint32_t a1, uint32_t a2, uint32_t a3,
                                           uint32_t b0, uint32_t b1) {
    asm volatile("mma.sync.aligned.m16n8k16.row.col.f32.f16.f16.f32 "
        "{%0,%1,%2,%3}, {%4,%5,%6,%7}, {%8,%9}, {%0,%1,%2,%3};"
        : "+f"(d0), "+f"(d1), "+f"(d2), "+f"(d3)
        : "r"(a0), "r"(a1), "r"(a2), "r"(a3), "r"(b0), "r"(b1));
}

#define CP_ASYNC16(dst, src) \
    asm volatile("cp.async.cg.shared.global [%0], [%1], 16;" :: "r"(dst), "l"(src))
#define CP_COMMIT() asm volatile("cp.async.commit_group;" ::: "memory")
#define CP_WAIT(n)  asm volatile("cp.async.wait_group %0;" :: "n"(n) : "memory")

// ===========================================================================
// Kernel 0: convert W matrices to fp16, per-chunk swizzled tiles.
// ===========================================================================
__global__ __launch_bounds__(256) void split_w_kernel(
    const float* __restrict__ Wq, const float* __restrict__ Wk, const float* __restrict__ Wv)
{
    const int ck = blockIdx.x, m = blockIdx.y, tid = threadIdx.x;
    const float4* W4 = (const float4*)((m == 0) ? Wq : ((m == 1) ? Wk : Wv));
    char* hiB = (char*)g_wh[m] + ck * 8192;
    #pragma unroll
    for (int j = 0; j < 4; j++) {
        int f = tid + j * 256;
        int r = f >> 4, c4 = f & 15;
        float4 v = W4[(size_t)(ck * 64 + r) * 16 + c4];
        uint32_t so = (uint32_t)(r * 128 + (((c4 >> 1) ^ (r & 7)) << 4) + (c4 & 1) * 8);
        *(uint32_t*)(hiB + so)     = packhf(v.x, v.y);
        *(uint32_t*)(hiB + so + 4) = packhf(v.z, v.w);
    }
}

// ===========================================================================
// Kernel 1: fused QKV projection + LayerNorm, fp16x2 (X hi/lo, W single).
// ===========================================================================
#define P_XHI 0
#define P_XLO 16384
#define P_WH  32768
#define P_WSTRIDE 8192
#define PROJ_SMEM (32768 + 3 * 8192)

__global__ __launch_bounds__(256) void proj_ln_kernel(const float* __restrict__ X)
{
    extern __shared__ char smem[];
    const uint32_t sb = smem_u32(smem);
    const int tid  = threadIdx.x;
    const int warp = tid >> 5, lane = tid & 31;
    const int wrow = warp * 16;
    const int mt   = blockIdx.x;

    float a0[3][8], a1[3][8], a2[3][8], a3[3][8];
    #pragma unroll
    for (int m = 0; m < 3; m++)
        #pragma unroll
        for (int nc = 0; nc < 8; nc++) { a0[m][nc]=0.f; a1[m][nc]=0.f; a2[m][nc]=0.f; a3[m][nc]=0.f; }

    const float4* X4 = (const float4*)X;

    const int arow = wrow + (lane & 15);
    const int as7  = arow & 7;
    const int abit = lane >> 4;
    const int krv  = lane & 15;
    const int vbit = lane >> 4;
    const int s7   = lane & 7;

    for (int kk = 0; kk < D_; kk += 64) {
        __syncthreads();

        // W tiles via cp.async (pre-converted fp16, already swizzled)
        #pragma unroll
        for (int m = 0; m < 3; m++) {
            const char* srcH = (const char*)g_wh[m] + (kk >> 6) * 8192;
            #pragma unroll
            for (int j = 0; j < 2; j++) {
                int f16 = (tid + j * 256) * 16;
                CP_ASYNC16(sb + P_WH + (uint32_t)(m * P_WSTRIDE) + f16, srcH + f16);
            }
        }
        CP_COMMIT();

        // X chunk [128 x 64] -> fp16 hi/lo, swizzled
        #pragma unroll
        for (int j = 0; j < 8; j++) {
            int f = tid + j * 256;
            int r = f >> 4, c4 = f & 15;
            float4 v = X4[(size_t)(mt * 128 + r) * 256 + (kk >> 2) + c4];
            uint32_t h0, l0, h1, l1;
            split2h(v.x, v.y, h0, l0);
            split2h(v.z, v.w, h1, l1);
            uint32_t so = (uint32_t)(r * 128 + (((c4 >> 1) ^ (r & 7)) << 4) + (c4 & 1) * 8);
            *(uint32_t*)(smem + P_XHI + so)     = h0;
            *(uint32_t*)(smem + P_XHI + so + 4) = h1;
            *(uint32_t*)(smem + P_XLO + so)     = l0;
            *(uint32_t*)(smem + P_XLO + so + 4) = l1;
        }
        CP_WAIT(0);
        __syncthreads();

        uint32_t xh[4][4], xl[4][4];
        #pragma unroll
        for (int kc = 0; kc < 4; kc++) {
            int c16 = 2 * kc + abit;
            uint32_t ad = sb + P_XHI + (uint32_t)(arow * 128) + ((c16 ^ as7) << 4);
            ldsm4(xh[kc][0], xh[kc][1], xh[kc][2], xh[kc][3], ad);
            ldsm4(xl[kc][0], xl[kc][1], xl[kc][2], xl[kc][3], ad + (P_XLO - P_XHI));
        }

        #pragma unroll
        for (int m = 0; m < 3; m++) {
            uint32_t wbase = sb + P_WH + (uint32_t)(m * P_WSTRIDE);
            #pragma unroll
            for (int kc = 0; kc < 4; kc++) {
                #pragma unroll
                for (int ncp = 0; ncp < 4; ncp++) {
                    uint32_t ad = wbase + (uint32_t)((kc * 16 + krv) * 128)
                                + (((2 * ncp + vbit) ^ s7) << 4);
                    uint32_t bh0, bh1, bh2, bh3;
                    ldsm4t(bh0, bh1, bh2, bh3, ad);
                    int n = 2 * ncp;
                    mma16816h(a0[m][n], a1[m][n], a2[m][n], a3[m][n],
                              xh[kc][0], xh[kc][1], xh[kc][2], xh[kc][3], bh0, bh1);
                    mma16816h(a0[m][n], a1[m][n], a2[m][n], a3[m][n],
                              xl[kc][0], xl[kc][1], xl[kc][2], xl[kc][3], bh0, bh1);
                    mma16816h(a0[m][n+1], a1[m][n+1], a2[m][n+1], a3[m][n+1],
                              xh[kc][0], xh[kc][1], xh[kc][2], xh[kc][3], bh2, bh3);
                    mma16816h(a0[m][n+1], a1[m][n+1], a2[m][n+1], a3[m][n+1],
                              xl[kc][0], xl[kc][1], xl[kc][2], xl[kc][3], bh2, bh3);
                }
            }
        }
    }

    // ---- epilogue: LayerNorm (Q,K); store q/k/v fp16 ----
    const int rA = mt * 128 + wrow + (lane >> 2);
    const int rB = rA + 8;

    #pragma unroll
    for (int m = 0; m < 3; m++) {
        float mu0 = 0.f, mu1 = 0.f, rs0 = 1.f, rs1 = 1.f;
        if (m < 2) {
            float sum0 = 0.f, sum1 = 0.f;
            #pragma unroll
            for (int nc = 0; nc < 8; nc++) {
                sum0 += a0[m][nc] + a1[m][nc];
                sum1 += a2[m][nc] + a3[m][nc];
            }
            sum0 += __shfl_xor_sync(0xffffffffu, sum0, 1);
            sum0 += __shfl_xor_sync(0xffffffffu, sum0, 2);
            sum1 += __shfl_xor_sync(0xffffffffu, sum1, 1);
            sum1 += __shfl_xor_sync(0xffffffffu, sum1, 2);
            mu0 = sum0 * (1.0f / 64.0f);
            mu1 = sum1 * (1.0f / 64.0f);
            float v0 = 0.f, v1 = 0.f;
            #pragma unroll
            for (int nc = 0; nc < 8; nc++) {
                float d00 = a0[m][nc] - mu0, d01 = a1[m][nc] - mu0;
                float d10 = a2[m][nc] - mu1, d11 = a3[m][nc] - mu1;
                v0 += d00 * d00 + d01 * d01;
                v1 += d10 * d10 + d11 * d11;
            }
            v0 += __shfl_xor_sync(0xffffffffu, v0, 1);
            v0 += __shfl_xor_sync(0xffffffffu, v0, 2);
            v1 += __shfl_xor_sync(0xffffffffu, v1, 1);
            v1 += __shfl_xor_sync(0xffffffffu, v1, 2);
            rs0 = rsqrtf(v0 * (1.0f / 64.0f) + 1e-5f);
            rs1 = rsqrtf(v1 * (1.0f / 64.0f) + 1e-5f);
        }

        uint32_t* g32 = (uint32_t*)((m == 0) ? g_qh : ((m == 1) ? g_kh : g_vh));
        #pragma unroll
        for (int nc = 0; nc < 8; nc++) {
            uint32_t hA = packhf((a0[m][nc] - mu0) * rs0, (a1[m][nc] - mu0) * rs0);
            uint32_t hB = packhf((a2[m][nc] - mu1) * rs1, (a3[m][nc] - mu1) * rs1);
            size_t iA = (size_t)rA * 32 + nc * 4 + (lane & 3);
            size_t iB = (size_t)rB * 32 + nc * 4 + (lane & 3);
            g32[iA] = hA;
            g32[iB] = hB;
        }
    }
}

// ===========================================================================
// Kernel 2: flash attention, fp16 mma 1-pass QK + 1-pass PV.
// Fixed-reference softmax (|s| <= 8 guaranteed by LayerNorm + Cauchy-Schwarz):
// no online max, no rescale; l reduced once at the end.
// ===========================================================================
#define OFF_KHI 0
#define OFF_VHI 16384
#define TB      32768
#define NT      (S_ / 128)
#define ATTN_SMEM (2 * TB)

__global__ __launch_bounds__(256) void attn_mma_kernel(float* __restrict__ out)
{
    extern __shared__ char smem[];
    const uint32_t sb = smem_u32(smem);
    const int tid  = threadIdx.x;
    const int warp = tid >> 5, lane = tid & 31;
    const int wrow = warp * 16;

    const int qbase = blockIdx.x * 128;
    const int b     = qbase / S_;

    // ---- stage Q into buf0 (K area), grab A fragments ----
    {
        const uint4* qh4 = (const uint4*)((const char*)g_qh + (size_t)qbase * 128);
        #pragma unroll
        for (int j = 0; j < 4; j++) {
            int f = tid + j * 256;
            int r = f >> 3, c = f & 7;
            uint32_t so = r * 128 + ((c ^ (r & 7)) << 4);
            *(uint4*)(smem + OFF_KHI + so) = qh4[f];
        }
    }
    __syncthreads();

    uint32_t qh[4][4];
    {
        int arow = wrow + (lane & 15);
        int as7  = arow & 7;
        #pragma unroll
        for (int kc = 0; kc < 4; kc++) {
            int c16 = 2 * kc + (lane >> 4);
            uint32_t ad = sb + OFF_KHI + arow * 128 + ((c16 ^ as7) << 4);
            ldsm4(qh[kc][0], qh[kc][1], qh[kc][2], qh[kc][3], ad);
        }
    }
    __syncthreads();

    const char* khB = (const char*)g_kh + (size_t)(b * S_) * 128;
    const char* vhB = (const char*)g_vh + (size_t)(b * S_) * 128;

    // prefetch tile 0 -> buf 0
    {
        #pragma unroll
        for (int j = 0; j < 4; j++) {
            int f = tid + j * 256;
            int r = f >> 3, c = f & 7;
            uint32_t so = r * 128 + ((c ^ (r & 7)) << 4);
            int gs = f * 16;
            CP_ASYNC16(sb + OFF_KHI + so, khB + gs);
            CP_ASYNC16(sb + OFF_VHI + so, vhB + gs);
        }
        CP_COMMIT();
    }

    float s0[16], s1[16], s2[16], s3[16];
    float o0[8], o1[8], o2[8], o3[8];
    #pragma unroll
    for (int i = 0; i < 8; i++) { o0[i] = 0.f; o1[i] = 0.f; o2[i] = 0.f; o3[i] = 0.f; }
    float l0 = 0.f, l1 = 0.f;

    const int s7   = lane & 7;
    const int krq  = (lane & 7) + ((lane >> 4) << 3);
    const int cbit = (lane >> 3) & 1;
    const int krv  = lane & 15;
    const int vbit = lane >> 4;
    // p = exp(0.125 * s) = 2^(s * 0.125 * log2(e))
    const float C = 0.125f * 1.44269504088896f;

    for (int kt = 0; kt < NT; kt++) {
        __syncthreads();

        if (kt + 1 < NT) {
            uint32_t dst = sb + ((kt + 1) & 1) * TB;
            size_t gb = (size_t)((kt + 1) * 128) * 128;
            #pragma unroll
            for (int j = 0; j < 4; j++) {
                int f = tid + j * 256;
                int r = f >> 3, c = f & 7;
                uint32_t so = r * 128 + ((c ^ (r & 7)) << 4);
                size_t gs = gb + f * 16;
                CP_ASYNC16(dst + OFF_KHI + so, khB + gs);
                CP_ASYNC16(dst + OFF_VHI + so, vhB + gs);
            }
            CP_COMMIT();
            CP_WAIT(1);
        } else {
            CP_WAIT(0);
        }
        __syncthreads();

        const uint32_t bufb = sb + (kt & 1) * TB;

        // ---- S = Q K^T (1 fp16 pass) ----
        #pragma unroll
        for (int i = 0; i < 16; i++) { s0[i] = 0.f; s1[i] = 0.f; s2[i] = 0.f; s3[i] = 0.f; }
        #pragma unroll
        for (int kc = 0; kc < 4; kc++) {
            #pragma unroll
            for (int ncp = 0; ncp < 8; ncp++) {
                uint32_t ad = bufb + OFF_KHI + (uint32_t)(ncp * 16 + krq) * 128
                            + (((2 * kc + cbit) ^ s7) << 4);
                uint32_t bh0, bh1, bh2, bh3;
                ldsm4(bh0, bh1, bh2, bh3, ad);
                int n = 2 * ncp;
                mma16816h(s0[n], s1[n], s2[n], s3[n], qh[kc][0], qh[kc][1], qh[kc][2], qh[kc][3], bh0, bh1);
                mma16816h(s0[n+1], s1[n+1], s2[n+1], s3[n+1], qh[kc][0], qh[kc][1], qh[kc][2], qh[kc][3], bh2, bh3);
            }
        }

        // ---- p = exp2(s*C); accumulate l locally (no reductions, no rescale) ----
        #pragma unroll
        for (int i = 0; i < 16; i++) {
            s0[i] = ex2f(s0[i] * C); s1[i] = ex2f(s1[i] * C);
            s2[i] = ex2f(s2[i] * C); s3[i] = ex2f(s3[i] * C);
            l0 += s0[i] + s1[i];
            l1 += s2[i] + s3[i];
        }

        // ---- O += P V (1 fp16 pass) ----
        #pragma unroll
        for (int kc = 0; kc < 8; kc++) {
            uint32_t ph0 = packhf(s0[2*kc],   s1[2*kc]);
            uint32_t ph1 = packhf(s2[2*kc],   s3[2*kc]);
            uint32_t ph2 = packhf(s0[2*kc+1], s1[2*kc+1]);
            uint32_t ph3 = packhf(s2[2*kc+1], s3[2*kc+1]);
            #pragma unroll
            for (int ncp = 0; ncp < 4; ncp++) {
                uint32_t ad = bufb + OFF_VHI + (uint32_t)(kc * 16 + krv) * 128
                            + (((2 * ncp + vbit) ^ s7) << 4);
                uint32_t bh0, bh1, bh2, bh3;
                ldsm4t(bh0, bh1, bh2, bh3, ad);
                int n = 2 * ncp;
                mma16816h(o0[n], o1[n], o2[n], o3[n], ph0, ph1, ph2, ph3, bh0, bh1);
                mma16816h(o0[n+1], o1[n+1], o2[n+1], o3[n+1], ph0, ph1, ph2, ph3, bh2, bh3);
            }
        }
    }

    // ---- final l reduction across the 4-lane quad, normalize, store ----
    l0 += __shfl_xor_sync(0xffffffffu, l0, 1);
    l0 += __shfl_xor_sync(0xffffffffu, l0, 2);
    l1 += __shfl_xor_sync(0xffffffffu, l1, 1);
    l1 += __shfl_xor_sync(0xffffffffu, l1, 2);

    const float il0 = 1.0f / l0, il1 = 1.0f / l1;
    const int r  = lane >> 2;
    const int c2 = (lane & 3) * 2;
    float2* out2 = (float2*)out;
    #pragma unroll
    for (int nc = 0; nc < 8; nc++) {
        size_t i_lo = ((size_t)(qbase + wrow + r)     * 64 + 8 * nc + c2) >> 1;
        size_t i_hi = ((size_t)(qbase + wrow + r + 8) * 64 + 8 * nc + c2) >> 1;
        out2[i_lo] = make_float2(o0[nc] * il0, o1[nc] * il0);
        out2[i_hi] = make_float2(o2[nc] * il1, o3[nc] * il1);
    }
}

// ===========================================================================
// Launch
// ===========================================================================
extern "C" void kernel_launch(void* const* d_in, const int* in_sizes, int n_in,
                              void* d_out, int out_size)
{
    const float* X  = (const float*)d_in[0];
    const float* Wq = (const float*)d_in[1];
    const float* Wk = (const float*)d_in[2];
    const float* Wv = (const float*)d_in[3];
    float* out = (float*)d_out;

    dim3 gw(16, 3);
    split_w_kernel<<<gw, 256>>>(Wq, Wk, Wv);

    cudaFuncSetAttribute(proj_ln_kernel, cudaFuncAttributeMaxDynamicSharedMemorySize, PROJ_SMEM);
    proj_ln_kernel<<<NROWS / 128, 256, PROJ_SMEM>>>(X);

    cudaFuncSetAttribute(attn_mma_kernel, cudaFuncAttributeMaxDynamicSharedMemorySize, ATTN_SMEM);
    attn_mma_kernel<<<NROWS / 128, 256, ATTN_SMEM>>>(out);
}